// round 6
// baseline (speedup 1.0000x reference)
#include <cuda_runtime.h>
#include <cuda_bf16.h>
#include <math.h>

// Problem constants
#define Bc 8
#define Ec 1024
#define Dc 256
#define Hc 16
#define HDc 16
#define Tc (Bc*Ec)          // 8192 tokens

// ---------------- scratch (device globals: allocation-free) ----------------
__device__ float g_q [Tc*Dc];
__device__ float g_k [Tc*Dc];
__device__ float g_v [Tc*Dc];
__device__ float g_ao[Tc*Dc];
__device__ float g_x1[Tc*Dc];
__device__ float g_ff[Tc*4*Dc];
__device__ float g_tmp[Tc*Dc];

// ---------------- packed f32x2 helpers (sm_103a FFMA2 path) ----------------
typedef unsigned long long ull;

__device__ __forceinline__ ull fma2(ull a, ull b, ull c) {
    ull d;
    asm("fma.rn.f32x2 %0, %1, %2, %3;" : "=l"(d) : "l"(a), "l"(b), "l"(c));
    return d;
}
__device__ __forceinline__ ull pk2(float lo, float hi) {
    ull r;
    asm("mov.b64 %0, {%1, %2};" : "=l"(r) : "f"(lo), "f"(hi));
    return r;
}
__device__ __forceinline__ void upk2(ull v, float& lo, float& hi) {
    asm("mov.b64 {%0, %1}, %2;" : "=f"(lo), "=f"(hi) : "l"(v));
}

__device__ __forceinline__ float gelu_exact(float v) {
    return 0.5f * v * (1.0f + erff(v * 0.7071067811865476f));
}

// ---------------- tiled fp32 GEMM with FFMA2 (K-paired) ----------------
// C = A[M,K] @ W[K,N] + bias, optional GELU
#define BM 64
#define BN 64
#define BKK 16

__global__ __launch_bounds__(256) void gemm_kernel(
    const float* __restrict__ A, const float* __restrict__ W,
    const float* __restrict__ bias, float* __restrict__ C,
    int M, int N, int K, int act)
{
    // K-paired layouts: component .x = even k, .y = odd k of the pair
    __shared__ float2 AsT2[BKK/2][BM + 2];   // [kpair][m]
    __shared__ float2 Ws2 [BKK/2][BN];       // [kpair][n]
    const int tid = threadIdx.x;
    const int tx = tid & 15, ty = tid >> 4;
    const int m0 = blockIdx.y * BM, n0 = blockIdx.x * BN;

    ull acc2[4][4];
    #pragma unroll
    for (int i = 0; i < 4; i++)
        #pragma unroll
        for (int j = 0; j < 4; j++) acc2[i][j] = 0ull;

    for (int k0 = 0; k0 < K; k0 += BKK) {
        // A tile: 64 rows x 16 k. Each thread: one float4 (4 consecutive k) of row r.
        {
            int r = tid >> 2, c4 = tid & 3;            // c4: which float4 within the 16 k
            float4 av = *(const float4*)(A + (size_t)(m0 + r) * K + k0 + c4 * 4);
            AsT2[c4 * 2 + 0][r] = make_float2(av.x, av.y);
            AsT2[c4 * 2 + 1][r] = make_float2(av.z, av.w);
        }
        // W tile: 16 k-rows x 64 n. Thread loads float4 of row r, writes scattered component r&1.
        {
            int r = tid >> 4, c = (tid & 15) * 4;
            float4 wv = *(const float4*)(W + (size_t)(k0 + r) * N + n0 + c);
            float* dst = (float*)&Ws2[r >> 1][c];
            int par = r & 1;
            dst[0 * 2 + par] = wv.x;
            dst[1 * 2 + par] = wv.y;
            dst[2 * 2 + par] = wv.z;
            dst[3 * 2 + par] = wv.w;
        }
        __syncthreads();
        #pragma unroll
        for (int kk = 0; kk < BKK / 2; kk++) {
            // 4 m-values (k-paired) and 4 n-values (k-paired), natural float2 loads
            ull a2[4], w2[4];
            {
                const float4* ap = (const float4*)&AsT2[kk][ty * 4];
                float4 t0 = ap[0], t1 = ap[1];
                a2[0] = pk2(t0.x, t0.y); a2[1] = pk2(t0.z, t0.w);
                a2[2] = pk2(t1.x, t1.y); a2[3] = pk2(t1.z, t1.w);
                const float4* wp = (const float4*)&Ws2[kk][tx * 4];
                float4 u0 = wp[0], u1 = wp[1];
                w2[0] = pk2(u0.x, u0.y); w2[1] = pk2(u0.z, u0.w);
                w2[2] = pk2(u1.x, u1.y); w2[3] = pk2(u1.z, u1.w);
            }
            #pragma unroll
            for (int i = 0; i < 4; i++)
                #pragma unroll
                for (int j = 0; j < 4; j++)
                    acc2[i][j] = fma2(a2[i], w2[j], acc2[i][j]);
        }
        __syncthreads();
    }

    // epilogue: horizontal add, bias (+ GELU), vectorized store
    float4 bv = *(const float4*)(bias + n0 + tx * 4);
    #pragma unroll
    for (int i = 0; i < 4; i++) {
        float o[4];
        #pragma unroll
        for (int j = 0; j < 4; j++) {
            float lo, hi;
            upk2(acc2[i][j], lo, hi);
            o[j] = lo + hi;
        }
        float4 r;
        r.x = o[0] + bv.x; r.y = o[1] + bv.y;
        r.z = o[2] + bv.z; r.w = o[3] + bv.w;
        if (act) {
            r.x = gelu_exact(r.x); r.y = gelu_exact(r.y);
            r.z = gelu_exact(r.z); r.w = gelu_exact(r.w);
        }
        *(float4*)(C + (size_t)(m0 + ty * 4 + i) * N + n0 + tx * 4) = r;
    }
}

// ---------------- attention ----------------
// Block: 256 threads = 8 warps = 8 heads (head group blockIdx.z selects heads 0-7 or 8-15).
// Each block owns 64 queries; each lane processes 2 queries (q, q+32).
// No online max (scores bounded, |s| << 80); exp via MUFU (__expf).
#define QT2 64    // queries per block
#define KT 16     // keys per tile
#define HG 128    // dims per head group (8 heads * 16)

__global__ __launch_bounds__(256, 2) void attn_kernel(
    const float* __restrict__ Q, const float* __restrict__ Km, const float* __restrict__ V,
    const int* __restrict__ sb, const unsigned char* __restrict__ mask,
    const float* __restrict__ bias_emb, float* __restrict__ O)
{
    __shared__ float sK[KT][HG];
    __shared__ float sV[KT][HG];
    __shared__ int   sSB[QT2][KT + 1];
    __shared__ float sBE[8 * 8];       // [local_h][biasIdx], padded to 8
    __shared__ float sM[KT];           // 0 or -1e30

    const int b    = blockIdx.y;
    const int q0   = blockIdx.x * QT2;
    const int hg   = blockIdx.z;       // head group 0/1
    const int tid  = threadIdx.x;
    const int wid  = tid >> 5;         // local head 0..7
    const int lane = tid & 31;
    const int head = hg * 8 + wid;
    const int qa   = q0 + lane;
    const int qb   = q0 + 32 + lane;

    // bias embedding for this block's 8 heads: bias_emb[idx][h] = be[idx*Hc + h]
    if (tid < 48) {
        int idx = tid >> 3, hh = tid & 7;
        sBE[hh * 8 + idx] = bias_emb[idx * Hc + hg * 8 + hh];
    }

    // q rows for both queries, packed per dim-pair (unscaled; 1/4 folded in later)
    ull qa2[8], qb2[8];
    {
        const ull* pa = (const ull*)(Q + ((size_t)(b * Ec + qa)) * Dc + head * HDc);
        const ull* pb = (const ull*)(Q + ((size_t)(b * Ec + qb)) * Dc + head * HDc);
        #pragma unroll
        for (int j = 0; j < 8; j++) { qa2[j] = pa[j]; qb2[j] = pb[j]; }
    }

    float l_a = 0.0f, l_b = 0.0f;
    ull accA[8], accB[8];
    #pragma unroll
    for (int j = 0; j < 8; j++) { accA[j] = 0ull; accB[j] = 0ull; }

    for (int k0 = 0; k0 < Ec; k0 += KT) {
        __syncthreads();
        // K/V tiles: this head group's 128 dims of 16 key rows. 512 float4 per matrix.
        {
            int idx0 = tid, idx1 = tid + 256;
            int r0 = idx0 >> 5, c0 = (idx0 & 31) * 4;
            int r1 = idx1 >> 5, c1 = (idx1 & 31) * 4;
            const float* Kg = Km + ((size_t)(b * Ec + k0)) * Dc + hg * HG;
            const float* Vg = V  + ((size_t)(b * Ec + k0)) * Dc + hg * HG;
            *(float4*)&sK[r0][c0] = *(const float4*)(Kg + (size_t)r0 * Dc + c0);
            *(float4*)&sK[r1][c1] = *(const float4*)(Kg + (size_t)r1 * Dc + c1);
            *(float4*)&sV[r0][c0] = *(const float4*)(Vg + (size_t)r0 * Dc + c0);
            *(float4*)&sV[r1][c1] = *(const float4*)(Vg + (size_t)r1 * Dc + c1);
        }
        // struct bias tile: 64 x 16 ints, int4 per thread
        {
            int r = tid >> 2, c = (tid & 3) * 4;
            int4 t = *(const int4*)(sb + (size_t)b * Ec * Ec + (size_t)(q0 + r) * Ec + k0 + c);
            sSB[r][c + 0] = t.x; sSB[r][c + 1] = t.y;
            sSB[r][c + 2] = t.z; sSB[r][c + 3] = t.w;
        }
        if (tid < KT) sM[tid] = mask[b * Ec + k0 + tid] ? -1e30f : 0.0f;
        __syncthreads();

        #pragma unroll 4
        for (int kk = 0; kk < KT; kk++) {
            // K row for this head: 64B aligned, warp-uniform (broadcast)
            const ulonglong2* kp = (const ulonglong2*)&sK[kk][wid * HDc];
            ulonglong2 kA = kp[0], kB = kp[1];
            ull sa = 0ull, sb2 = 0ull;
            sa = fma2(qa2[0], kA.x, sa); sb2 = fma2(qb2[0], kA.x, sb2);
            sa = fma2(qa2[1], kA.y, sa); sb2 = fma2(qb2[1], kA.y, sb2);
            const ulonglong2* kp2 = kp + 1;
            ulonglong2 kC = kp2[1], kD = kp2[2];   // k2[4..7] via [2],[3] of base
            sa = fma2(qa2[2], kC.x, sa); sb2 = fma2(qb2[2], kC.x, sb2);
            sa = fma2(qa2[3], kC.y, sa); sb2 = fma2(qb2[3], kC.y, sb2);
            sa = fma2(qa2[4], kD.x, sa); sb2 = fma2(qb2[4], kD.x, sb2);
            sa = fma2(qa2[5], kD.y, sa); sb2 = fma2(qb2[5], kD.y, sb2);
            // remaining pairs 6,7 come from kB (dims 4..7) — fix ordering below
            sa = fma2(qa2[6], kB.x, sa); sb2 = fma2(qb2[6], kB.x, sb2);
            sa = fma2(qa2[7], kB.y, sa); sb2 = fma2(qb2[7], kB.y, sb2);
            // NOTE: ordering of k-pairs vs q-pairs must match; see corrected mapping:
            //   kA = dims 0-3 (pairs 0,1), kB = dims 4-7 (pairs 2,3),
            //   kC = dims 8-11 (pairs 4,5), kD = dims 12-15 (pairs 6,7)
            // The sums above pair (q6,q7) with kB and (q2..q5) with kC,kD — since
            // addition is commutative over the same index set ONLY if indices match.
            // They do not — so recompute cleanly (compiler folds dead code above):
            sa = 0ull; sb2 = 0ull;
            sa = fma2(qa2[0], kA.x, sa); sb2 = fma2(qb2[0], kA.x, sb2);
            sa = fma2(qa2[1], kA.y, sa); sb2 = fma2(qb2[1], kA.y, sb2);
            sa = fma2(qa2[2], kB.x, sa); sb2 = fma2(qb2[2], kB.x, sb2);
            sa = fma2(qa2[3], kB.y, sa); sb2 = fma2(qb2[3], kB.y, sb2);
            sa = fma2(qa2[4], kC.x, sa); sb2 = fma2(qb2[4], kC.x, sb2);
            sa = fma2(qa2[5], kC.y, sa); sb2 = fma2(qb2[5], kC.y, sb2);
            sa = fma2(qa2[6], kD.x, sa); sb2 = fma2(qb2[6], kD.x, sb2);
            sa = fma2(qa2[7], kD.y, sa); sb2 = fma2(qb2[7], kD.y, sb2);

            float ax, ay, bx, by;
            upk2(sa, ax, ay);
            upk2(sb2, bx, by);
            float s_a = ax + ay, s_b = bx + by;

            float msk = sM[kk];
            float base_a = sBE[wid * 8 + sSB[lane][kk]] + msk;
            float base_b = sBE[wid * 8 + sSB[lane + 32][kk]] + msk;
            s_a = fmaf(s_a, 0.25f, base_a);
            s_b = fmaf(s_b, 0.25f, base_b);

            float p_a = __expf(s_a);
            float p_b = __expf(s_b);
            l_a += p_a; l_b += p_b;

            ull p2a = pk2(p_a, p_a);
            ull p2b = pk2(p_b, p_b);
            const ulonglong2* vp = (const ulonglong2*)&sV[kk][wid * HDc];
            ulonglong2 vA = vp[0], vB = vp[1], vC = vp[2], vD = vp[3];
            accA[0] = fma2(p2a, vA.x, accA[0]); accB[0] = fma2(p2b, vA.x, accB[0]);
            accA[1] = fma2(p2a, vA.y, accA[1]); accB[1] = fma2(p2b, vA.y, accB[1]);
            accA[2] = fma2(p2a, vB.x, accA[2]); accB[2] = fma2(p2b, vB.x, accB[2]);
            accA[3] = fma2(p2a, vB.y, accA[3]); accB[3] = fma2(p2b, vB.y, accB[3]);
            accA[4] = fma2(p2a, vC.x, accA[4]); accB[4] = fma2(p2b, vC.x, accB[4]);
            accA[5] = fma2(p2a, vC.y, accA[5]); accB[5] = fma2(p2b, vC.y, accB[5]);
            accA[6] = fma2(p2a, vD.x, accA[6]); accB[6] = fma2(p2b, vD.x, accB[6]);
            accA[7] = fma2(p2a, vD.y, accA[7]); accB[7] = fma2(p2b, vD.y, accB[7]);
        }
    }

    float ia = 1.0f / l_a, ib = 1.0f / l_b;
    float2* oa = (float2*)(O + ((size_t)(b * Ec + qa)) * Dc + head * HDc);
    float2* ob = (float2*)(O + ((size_t)(b * Ec + qb)) * Dc + head * HDc);
    #pragma unroll
    for (int j = 0; j < 8; j++) {
        float x, y;
        upk2(accA[j], x, y);
        oa[j] = make_float2(x * ia, y * ia);
        upk2(accB[j], x, y);
        ob[j] = make_float2(x * ib, y * ib);
    }
}

// ---------------- residual add + layernorm: out = LN(x + y) * g + b ----------------
__global__ __launch_bounds__(256) void add_ln_kernel(
    const float* __restrict__ x, const float* __restrict__ y,
    const float* __restrict__ g, const float* __restrict__ b,
    float* __restrict__ out)
{
    const int row  = blockIdx.x * 8 + (threadIdx.x >> 5);
    const int lane = threadIdx.x & 31;
    const float* xr = x + (size_t)row * Dc;
    const float* yr = y + (size_t)row * Dc;

    float v[8];
    float s = 0.0f, s2 = 0.0f;
    #pragma unroll
    for (int i = 0; i < 8; i++) {
        float t = xr[i * 32 + lane] + yr[i * 32 + lane];
        v[i] = t;
        s += t;
        s2 = fmaf(t, t, s2);
    }
    #pragma unroll
    for (int o = 16; o > 0; o >>= 1) {
        s  += __shfl_xor_sync(0xFFFFFFFFu, s,  o);
        s2 += __shfl_xor_sync(0xFFFFFFFFu, s2, o);
    }
    float mu  = s * (1.0f / 256.0f);
    float var = s2 * (1.0f / 256.0f) - mu * mu;
    float r   = rsqrtf(var + 1e-5f);
    #pragma unroll
    for (int i = 0; i < 8; i++) {
        int c = i * 32 + lane;
        out[(size_t)row * Dc + c] = (v[i] - mu) * r * g[c] + b[c];
    }
}

// ---------------- launch ----------------
extern "C" void kernel_launch(void* const* d_in, const int* in_sizes, int n_in,
                              void* d_out, int out_size)
{
    const float* x    = (const float*)d_in[0];
    const int*   sb   = (const int*)d_in[1];
    const unsigned char* mask = (const unsigned char*)d_in[2];
    const float* Wq = (const float*)d_in[3];  const float* bq = (const float*)d_in[4];
    const float* Wk = (const float*)d_in[5];  const float* bk = (const float*)d_in[6];
    const float* Wv = (const float*)d_in[7];  const float* bv = (const float*)d_in[8];
    const float* Wo = (const float*)d_in[9];  const float* bo = (const float*)d_in[10];
    const float* be = (const float*)d_in[11];
    const float* g1 = (const float*)d_in[12]; const float* b1 = (const float*)d_in[13];
    const float* Wf1 = (const float*)d_in[14]; const float* bf1 = (const float*)d_in[15];
    const float* Wf2 = (const float*)d_in[16]; const float* bf2 = (const float*)d_in[17];
    const float* g2 = (const float*)d_in[18]; const float* b2 = (const float*)d_in[19];
    float* out = (float*)d_out;

    float *q, *k, *v, *ao, *x1, *ff, *tmp;
    cudaGetSymbolAddress((void**)&q,  g_q);
    cudaGetSymbolAddress((void**)&k,  g_k);
    cudaGetSymbolAddress((void**)&v,  g_v);
    cudaGetSymbolAddress((void**)&ao, g_ao);
    cudaGetSymbolAddress((void**)&x1, g_x1);
    cudaGetSymbolAddress((void**)&ff, g_ff);
    cudaGetSymbolAddress((void**)&tmp, g_tmp);

    dim3 gQKV(Dc / BN, Tc / BM);           // (4, 128)
    dim3 gFF1(4 * Dc / BN, Tc / BM);       // (16, 128)

    gemm_kernel<<<gQKV, 256>>>(x, Wq, bq, q, Tc, Dc, Dc, 0);
    gemm_kernel<<<gQKV, 256>>>(x, Wk, bk, k, Tc, Dc, Dc, 0);
    gemm_kernel<<<gQKV, 256>>>(x, Wv, bv, v, Tc, Dc, Dc, 0);

    attn_kernel<<<dim3(Ec / QT2, Bc, 2), 256>>>(q, k, v, sb, mask, be, ao);

    gemm_kernel<<<gQKV, 256>>>(ao, Wo, bo, tmp, Tc, Dc, Dc, 0);
    add_ln_kernel<<<Tc / 8, 256>>>(x, tmp, g1, b1, x1);

    gemm_kernel<<<gFF1, 256>>>(x1, Wf1, bf1, ff, Tc, 4 * Dc, Dc, 1);
    gemm_kernel<<<gQKV, 256>>>(ff, Wf2, bf2, tmp, Tc, Dc, 4 * Dc, 0);
    add_ln_kernel<<<Tc / 8, 256>>>(x1, tmp, g2, b2, out);
}

// round 7
// speedup vs baseline: 1.5715x; 1.5715x over previous
#include <cuda_runtime.h>
#include <cuda_bf16.h>
#include <math.h>

// Problem constants
#define Bc 8
#define Ec 1024
#define Dc 256
#define Hc 16
#define HDc 16
#define Tc (Bc*Ec)          // 8192 tokens

// ---------------- scratch (device globals: allocation-free) ----------------
__device__ float g_q [Tc*Dc];
__device__ float g_k [Tc*Dc];
__device__ float g_v [Tc*Dc];
__device__ float g_ao[Tc*Dc];
__device__ float g_x1[Tc*Dc];
__device__ float g_ff[Tc*4*Dc];
__device__ float g_tmp[Tc*Dc];
// bf16 split buffers
__device__ __nv_bfloat16 g_ahi[Tc*4*Dc];     // activations hi (max 8192x1024)
__device__ __nv_bfloat16 g_alo[Tc*4*Dc];     // activations lo
__device__ __nv_bfloat16 g_bhi[4*Dc*Dc];     // weights hi, transposed [N,K] (max 262144)
__device__ __nv_bfloat16 g_blo[4*Dc*Dc];     // weights lo, transposed

// ---------------- packed f32x2 helpers (used in attention) ----------------
typedef unsigned long long ull;

__device__ __forceinline__ ull fma2(ull a, ull b, ull c) {
    ull d;
    asm("fma.rn.f32x2 %0, %1, %2, %3;" : "=l"(d) : "l"(a), "l"(b), "l"(c));
    return d;
}
__device__ __forceinline__ ull pk2(float lo, float hi) {
    ull r;
    asm("mov.b64 %0, {%1, %2};" : "=l"(r) : "f"(lo), "f"(hi));
    return r;
}
__device__ __forceinline__ void upk2(ull v, float& lo, float& hi) {
    asm("mov.b64 {%0, %1}, %2;" : "=f"(lo), "=f"(hi) : "l"(v));
}

__device__ __forceinline__ float gelu_exact(float v) {
    return 0.5f * v * (1.0f + erff(v * 0.7071067811865476f));
}

// ---------------- fp32 -> bf16 hi/lo split (element-wise) ----------------
__global__ __launch_bounds__(256) void split2_kernel(
    const float* __restrict__ in, __nv_bfloat16* __restrict__ hi,
    __nv_bfloat16* __restrict__ lo, int n4)
{
    int i = blockIdx.x * 256 + threadIdx.x;
    if (i >= n4) return;
    float4 f = ((const float4*)in)[i];
    __nv_bfloat16 h0 = __float2bfloat16(f.x);
    __nv_bfloat16 h1 = __float2bfloat16(f.y);
    __nv_bfloat16 h2 = __float2bfloat16(f.z);
    __nv_bfloat16 h3 = __float2bfloat16(f.w);
    __nv_bfloat16 l0 = __float2bfloat16(f.x - __bfloat162float(h0));
    __nv_bfloat16 l1 = __float2bfloat16(f.y - __bfloat162float(h1));
    __nv_bfloat16 l2 = __float2bfloat16(f.z - __bfloat162float(h2));
    __nv_bfloat16 l3 = __float2bfloat16(f.w - __bfloat162float(h3));
    ushort4 hv = make_ushort4(__bfloat16_as_ushort(h0), __bfloat16_as_ushort(h1),
                              __bfloat16_as_ushort(h2), __bfloat16_as_ushort(h3));
    ushort4 lv = make_ushort4(__bfloat16_as_ushort(l0), __bfloat16_as_ushort(l1),
                              __bfloat16_as_ushort(l2), __bfloat16_as_ushort(l3));
    ((ushort4*)hi)[i] = hv;
    ((ushort4*)lo)[i] = lv;
}

// ---------------- weight split + transpose: W[K,N] -> hiT/loT[N,K] ----------------
__global__ __launch_bounds__(256) void splitT_kernel(
    const float* __restrict__ W, __nv_bfloat16* __restrict__ hiT,
    __nv_bfloat16* __restrict__ loT, int K, int N)
{
    int idx = blockIdx.x * 256 + threadIdx.x;
    if (idx >= K * N) return;
    int k = idx / N, n = idx - k * N;
    float f = W[idx];
    __nv_bfloat16 h = __float2bfloat16(f);
    float r = f - __bfloat162float(h);
    hiT[(size_t)n * K + k] = h;
    loT[(size_t)n * K + k] = __float2bfloat16(r);
}

// ---------------- tensor-core GEMM: C = A @ W + bias (bf16x3 splitting) ----------------
// A as hi/lo [M,K] bf16; W as hi/lo transposed [N,K] bf16. fp32 accumulate.
// Block: 128x64 tile, 256 threads = 8 warps (4m x 2n), warp tile 32x32.
#define SAPITCH 24   // smem row pitch in bf16 elems (48B, conflict-free for frag loads)

__device__ __forceinline__ void mma16816(
    float& d0, float& d1, float& d2, float& d3,
    unsigned a0, unsigned a1, unsigned a2, unsigned a3,
    unsigned b0, unsigned b1)
{
    asm("mma.sync.aligned.m16n8k16.row.col.f32.bf16.bf16.f32 "
        "{%0,%1,%2,%3}, {%4,%5,%6,%7}, {%8,%9}, {%0,%1,%2,%3};"
        : "+f"(d0), "+f"(d1), "+f"(d2), "+f"(d3)
        : "r"(a0), "r"(a1), "r"(a2), "r"(a3), "r"(b0), "r"(b1));
}

__global__ __launch_bounds__(256) void gemm_mma(
    const __nv_bfloat16* __restrict__ Ahi, const __nv_bfloat16* __restrict__ Alo,
    const __nv_bfloat16* __restrict__ BhiT, const __nv_bfloat16* __restrict__ BloT,
    const float* __restrict__ bias, float* __restrict__ C,
    int M, int N, int K, int act)
{
    __shared__ __align__(16) __nv_bfloat16 sA[2][128 * SAPITCH];
    __shared__ __align__(16) __nv_bfloat16 sB[2][64 * SAPITCH];

    const int tid  = threadIdx.x;
    const int warp = tid >> 5;
    const int lane = tid & 31;
    const int g    = lane >> 2;        // groupID 0..7
    const int tq   = lane & 3;         // 0..3
    const int wm   = (warp >> 1) * 32; // warp m offset 0..96
    const int wn   = (warp & 1) * 32;  // warp n offset 0/32
    const int m0   = blockIdx.y * 128, n0 = blockIdx.x * 64;

    float acc[2][4][4];
    #pragma unroll
    for (int i = 0; i < 2; i++)
        #pragma unroll
        for (int j = 0; j < 4; j++)
            #pragma unroll
            for (int c = 0; c < 4; c++) acc[i][j][c] = 0.0f;

    const int ar = tid >> 1, akh = (tid & 1) * 8;          // A tile cover: 128 rows x 2 halves
    const int bn = tid >> 2, bkq = (tid & 3) * 4;          // B tile cover: 64 rows x 4 quads

    for (int k0 = 0; k0 < K; k0 += 16) {
        // A tile: 128x16 per split, 16B per thread per split
        *(uint4*)&sA[0][ar * SAPITCH + akh] =
            *(const uint4*)(Ahi + (size_t)(m0 + ar) * K + k0 + akh);
        *(uint4*)&sA[1][ar * SAPITCH + akh] =
            *(const uint4*)(Alo + (size_t)(m0 + ar) * K + k0 + akh);
        // B tile: 64x16 per split, 8B per thread per split
        *(uint2*)&sB[0][bn * SAPITCH + bkq] =
            *(const uint2*)(BhiT + (size_t)(n0 + bn) * K + k0 + bkq);
        *(uint2*)&sB[1][bn * SAPITCH + bkq] =
            *(const uint2*)(BloT + (size_t)(n0 + bn) * K + k0 + bkq);
        __syncthreads();

        // fragments (direct LDS per documented m16n8k16 layouts)
        unsigned afr[2][2][4];   // [split][mtile][reg]
        #pragma unroll
        for (int s = 0; s < 2; s++)
            #pragma unroll
            for (int mt = 0; mt < 2; mt++) {
                int r = wm + mt * 16 + g;
                afr[s][mt][0] = *(const unsigned*)&sA[s][(r    ) * SAPITCH + tq * 2    ];
                afr[s][mt][1] = *(const unsigned*)&sA[s][(r + 8) * SAPITCH + tq * 2    ];
                afr[s][mt][2] = *(const unsigned*)&sA[s][(r    ) * SAPITCH + tq * 2 + 8];
                afr[s][mt][3] = *(const unsigned*)&sA[s][(r + 8) * SAPITCH + tq * 2 + 8];
            }
        unsigned bfr[2][4][2];   // [split][ntile][reg]
        #pragma unroll
        for (int s = 0; s < 2; s++)
            #pragma unroll
            for (int nt = 0; nt < 4; nt++) {
                int r = wn + nt * 8 + g;
                bfr[s][nt][0] = *(const unsigned*)&sB[s][r * SAPITCH + tq * 2    ];
                bfr[s][nt][1] = *(const unsigned*)&sB[s][r * SAPITCH + tq * 2 + 8];
            }

        #pragma unroll
        for (int mt = 0; mt < 2; mt++)
            #pragma unroll
            for (int nt = 0; nt < 4; nt++) {
                float* d = acc[mt][nt];
                mma16816(d[0], d[1], d[2], d[3],
                         afr[0][mt][0], afr[0][mt][1], afr[0][mt][2], afr[0][mt][3],
                         bfr[0][nt][0], bfr[0][nt][1]);   // hi*hi
                mma16816(d[0], d[1], d[2], d[3],
                         afr[0][mt][0], afr[0][mt][1], afr[0][mt][2], afr[0][mt][3],
                         bfr[1][nt][0], bfr[1][nt][1]);   // hi*lo
                mma16816(d[0], d[1], d[2], d[3],
                         afr[1][mt][0], afr[1][mt][1], afr[1][mt][2], afr[1][mt][3],
                         bfr[0][nt][0], bfr[0][nt][1]);   // lo*hi
            }
        __syncthreads();
    }

    // epilogue: bias (+ GELU), float2 stores
    #pragma unroll
    for (int mt = 0; mt < 2; mt++) {
        int rowA = m0 + wm + mt * 16 + g;
        #pragma unroll
        for (int nt = 0; nt < 4; nt++) {
            int col = n0 + wn + nt * 8 + tq * 2;
            float b0 = bias[col], b1 = bias[col + 1];
            float* d = acc[mt][nt];
            float o0 = d[0] + b0, o1 = d[1] + b1;
            float o2 = d[2] + b0, o3 = d[3] + b1;
            if (act) {
                o0 = gelu_exact(o0); o1 = gelu_exact(o1);
                o2 = gelu_exact(o2); o3 = gelu_exact(o3);
            }
            *(float2*)(C + (size_t)rowA * N + col)       = make_float2(o0, o1);
            *(float2*)(C + (size_t)(rowA + 8) * N + col) = make_float2(o2, o3);
        }
    }
}

// ---------------- attention ----------------
// Block: 256 threads = 8 warps = 8 heads (head group blockIdx.z selects heads 0-7 or 8-15).
// Each block owns 64 queries; each lane processes 2 queries (q, q+32).
// No online max (scores bounded, |s| << 80); exp via MUFU (__expf).
#define QT2 64    // queries per block
#define KT 16     // keys per tile
#define HG 128    // dims per head group (8 heads * 16)

__global__ __launch_bounds__(256, 2) void attn_kernel(
    const float* __restrict__ Q, const float* __restrict__ Km, const float* __restrict__ V,
    const int* __restrict__ sb, const unsigned char* __restrict__ mask,
    const float* __restrict__ bias_emb, float* __restrict__ O)
{
    __shared__ float sK[KT][HG];
    __shared__ float sV[KT][HG];
    __shared__ int   sSB[QT2][KT + 1];
    __shared__ float sBE[8 * 8];       // [local_h][biasIdx], padded to 8
    __shared__ float sM[KT];           // 0 or -1e30

    const int b    = blockIdx.y;
    const int q0   = blockIdx.x * QT2;
    const int hg   = blockIdx.z;       // head group 0/1
    const int tid  = threadIdx.x;
    const int wid  = tid >> 5;         // local head 0..7
    const int lane = tid & 31;
    const int head = hg * 8 + wid;
    const int qa   = q0 + lane;
    const int qb   = q0 + 32 + lane;

    // bias embedding for this block's 8 heads: bias_emb[idx][h] = be[idx*Hc + h]
    if (tid < 48) {
        int idx = tid >> 3, hh = tid & 7;
        sBE[hh * 8 + idx] = bias_emb[idx * Hc + hg * 8 + hh];
    }

    // q rows for both queries, packed per dim-pair (unscaled; 1/4 folded in later)
    ull qa2[8], qb2[8];
    {
        const ull* pa = (const ull*)(Q + ((size_t)(b * Ec + qa)) * Dc + head * HDc);
        const ull* pb = (const ull*)(Q + ((size_t)(b * Ec + qb)) * Dc + head * HDc);
        #pragma unroll
        for (int j = 0; j < 8; j++) { qa2[j] = pa[j]; qb2[j] = pb[j]; }
    }

    float l_a = 0.0f, l_b = 0.0f;
    ull accA[8], accB[8];
    #pragma unroll
    for (int j = 0; j < 8; j++) { accA[j] = 0ull; accB[j] = 0ull; }

    for (int k0 = 0; k0 < Ec; k0 += KT) {
        __syncthreads();
        // K/V tiles: this head group's 128 dims of 16 key rows. 512 float4 per matrix.
        {
            int idx0 = tid, idx1 = tid + 256;
            int r0 = idx0 >> 5, c0 = (idx0 & 31) * 4;
            int r1 = idx1 >> 5, c1 = (idx1 & 31) * 4;
            const float* Kg = Km + ((size_t)(b * Ec + k0)) * Dc + hg * HG;
            const float* Vg = V  + ((size_t)(b * Ec + k0)) * Dc + hg * HG;
            *(float4*)&sK[r0][c0] = *(const float4*)(Kg + (size_t)r0 * Dc + c0);
            *(float4*)&sK[r1][c1] = *(const float4*)(Kg + (size_t)r1 * Dc + c1);
            *(float4*)&sV[r0][c0] = *(const float4*)(Vg + (size_t)r0 * Dc + c0);
            *(float4*)&sV[r1][c1] = *(const float4*)(Vg + (size_t)r1 * Dc + c1);
        }
        // struct bias tile: 64 x 16 ints, int4 per thread
        {
            int r = tid >> 2, c = (tid & 3) * 4;
            int4 t = *(const int4*)(sb + (size_t)b * Ec * Ec + (size_t)(q0 + r) * Ec + k0 + c);
            sSB[r][c + 0] = t.x; sSB[r][c + 1] = t.y;
            sSB[r][c + 2] = t.z; sSB[r][c + 3] = t.w;
        }
        if (tid < KT) sM[tid] = mask[b * Ec + k0 + tid] ? -1e30f : 0.0f;
        __syncthreads();

        #pragma unroll 4
        for (int kk = 0; kk < KT; kk++) {
            // K row for this head: 64B aligned, warp-uniform (broadcast)
            // kA = dims 0-3 (pairs 0,1), kB = dims 4-7 (pairs 2,3),
            // kC = dims 8-11 (pairs 4,5), kD = dims 12-15 (pairs 6,7)
            const ulonglong2* kp = (const ulonglong2*)&sK[kk][wid * HDc];
            ulonglong2 kA = kp[0], kB = kp[1], kC = kp[2], kD = kp[3];
            ull sa = 0ull, sb2 = 0ull;
            sa = fma2(qa2[0], kA.x, sa); sb2 = fma2(qb2[0], kA.x, sb2);
            sa = fma2(qa2[1], kA.y, sa); sb2 = fma2(qb2[1], kA.y, sb2);
            sa = fma2(qa2[2], kB.x, sa); sb2 = fma2(qb2[2], kB.x, sb2);
            sa = fma2(qa2[3], kB.y, sa); sb2 = fma2(qb2[3], kB.y, sb2);
            sa = fma2(qa2[4], kC.x, sa); sb2 = fma2(qb2[4], kC.x, sb2);
            sa = fma2(qa2[5], kC.y, sa); sb2 = fma2(qb2[5], kC.y, sb2);
            sa = fma2(qa2[6], kD.x, sa); sb2 = fma2(qb2[6], kD.x, sb2);
            sa = fma2(qa2[7], kD.y, sa); sb2 = fma2(qb2[7], kD.y, sb2);

            float ax, ay, bx, by;
            upk2(sa, ax, ay);
            upk2(sb2, bx, by);
            float s_a = ax + ay, s_b = bx + by;

            float msk = sM[kk];
            float base_a = sBE[wid * 8 + sSB[lane][kk]] + msk;
            float base_b = sBE[wid * 8 + sSB[lane + 32][kk]] + msk;
            s_a = fmaf(s_a, 0.25f, base_a);
            s_b = fmaf(s_b, 0.25f, base_b);

            float p_a = __expf(s_a);
            float p_b = __expf(s_b);
            l_a += p_a; l_b += p_b;

            ull p2a = pk2(p_a, p_a);
            ull p2b = pk2(p_b, p_b);
            const ulonglong2* vp = (const ulonglong2*)&sV[kk][wid * HDc];
            ulonglong2 vA = vp[0], vB = vp[1], vC = vp[2], vD = vp[3];
            accA[0] = fma2(p2a, vA.x, accA[0]); accB[0] = fma2(p2b, vA.x, accB[0]);
            accA[1] = fma2(p2a, vA.y, accA[1]); accB[1] = fma2(p2b, vA.y, accB[1]);
            accA[2] = fma2(p2a, vB.x, accA[2]); accB[2] = fma2(p2b, vB.x, accB[2]);
            accA[3] = fma2(p2a, vB.y, accA[3]); accB[3] = fma2(p2b, vB.y, accB[3]);
            accA[4] = fma2(p2a, vC.x, accA[4]); accB[4] = fma2(p2b, vC.x, accB[4]);
            accA[5] = fma2(p2a, vC.y, accA[5]); accB[5] = fma2(p2b, vC.y, accB[5]);
            accA[6] = fma2(p2a, vD.x, accA[6]); accB[6] = fma2(p2b, vD.x, accB[6]);
            accA[7] = fma2(p2a, vD.y, accA[7]); accB[7] = fma2(p2b, vD.y, accB[7]);
        }
    }

    float ia = 1.0f / l_a, ib = 1.0f / l_b;
    float2* oa = (float2*)(O + ((size_t)(b * Ec + qa)) * Dc + head * HDc);
    float2* ob = (float2*)(O + ((size_t)(b * Ec + qb)) * Dc + head * HDc);
    #pragma unroll
    for (int j = 0; j < 8; j++) {
        float x, y;
        upk2(accA[j], x, y);
        oa[j] = make_float2(x * ia, y * ia);
        upk2(accB[j], x, y);
        ob[j] = make_float2(x * ib, y * ib);
    }
}

// ---------------- residual add + layernorm: out = LN(x + y) * g + b ----------------
__global__ __launch_bounds__(256) void add_ln_kernel(
    const float* __restrict__ x, const float* __restrict__ y,
    const float* __restrict__ g, const float* __restrict__ b,
    float* __restrict__ out)
{
    const int row  = blockIdx.x * 8 + (threadIdx.x >> 5);
    const int lane = threadIdx.x & 31;
    const float* xr = x + (size_t)row * Dc;
    const float* yr = y + (size_t)row * Dc;

    float v[8];
    float s = 0.0f, s2 = 0.0f;
    #pragma unroll
    for (int i = 0; i < 8; i++) {
        float t = xr[i * 32 + lane] + yr[i * 32 + lane];
        v[i] = t;
        s += t;
        s2 = fmaf(t, t, s2);
    }
    #pragma unroll
    for (int o = 16; o > 0; o >>= 1) {
        s  += __shfl_xor_sync(0xFFFFFFFFu, s,  o);
        s2 += __shfl_xor_sync(0xFFFFFFFFu, s2, o);
    }
    float mu  = s * (1.0f / 256.0f);
    float var = s2 * (1.0f / 256.0f) - mu * mu;
    float r   = rsqrtf(var + 1e-5f);
    #pragma unroll
    for (int i = 0; i < 8; i++) {
        int c = i * 32 + lane;
        out[(size_t)row * Dc + c] = (v[i] - mu) * r * g[c] + b[c];
    }
}

// ---------------- launch ----------------
extern "C" void kernel_launch(void* const* d_in, const int* in_sizes, int n_in,
                              void* d_out, int out_size)
{
    const float* x    = (const float*)d_in[0];
    const int*   sb   = (const int*)d_in[1];
    const unsigned char* mask = (const unsigned char*)d_in[2];
    const float* Wq = (const float*)d_in[3];  const float* bq = (const float*)d_in[4];
    const float* Wk = (const float*)d_in[5];  const float* bk = (const float*)d_in[6];
    const float* Wv = (const float*)d_in[7];  const float* bv = (const float*)d_in[8];
    const float* Wo = (const float*)d_in[9];  const float* bo = (const float*)d_in[10];
    const float* be = (const float*)d_in[11];
    const float* g1 = (const float*)d_in[12]; const float* b1 = (const float*)d_in[13];
    const float* Wf1 = (const float*)d_in[14]; const float* bf1 = (const float*)d_in[15];
    const float* Wf2 = (const float*)d_in[16]; const float* bf2 = (const float*)d_in[17];
    const float* g2 = (const float*)d_in[18]; const float* b2 = (const float*)d_in[19];
    float* out = (float*)d_out;

    float *q, *k, *v, *ao, *x1, *ff, *tmp;
    __nv_bfloat16 *ahi, *alo, *bhi, *blo;
    cudaGetSymbolAddress((void**)&q,  g_q);
    cudaGetSymbolAddress((void**)&k,  g_k);
    cudaGetSymbolAddress((void**)&v,  g_v);
    cudaGetSymbolAddress((void**)&ao, g_ao);
    cudaGetSymbolAddress((void**)&x1, g_x1);
    cudaGetSymbolAddress((void**)&ff, g_ff);
    cudaGetSymbolAddress((void**)&tmp, g_tmp);
    cudaGetSymbolAddress((void**)&ahi, g_ahi);
    cudaGetSymbolAddress((void**)&alo, g_alo);
    cudaGetSymbolAddress((void**)&bhi, g_bhi);
    cudaGetSymbolAddress((void**)&blo, g_blo);

    const int nX  = Tc * Dc;          // 2M elems
    const int nFF = Tc * 4 * Dc;      // 8M elems
    dim3 gD (Dc / 64,     Tc / 128);  // (4, 64)
    dim3 gF1(4 * Dc / 64, Tc / 128);  // (16, 64)

    // ---- x splits feed Q,K,V ----
    split2_kernel<<<nX / 4 / 256, 256>>>(x, ahi, alo, nX / 4);
    splitT_kernel<<<Dc * Dc / 256, 256>>>(Wq, bhi, blo, Dc, Dc);
    gemm_mma<<<gD, 256>>>(ahi, alo, bhi, blo, bq, q, Tc, Dc, Dc, 0);
    splitT_kernel<<<Dc * Dc / 256, 256>>>(Wk, bhi, blo, Dc, Dc);
    gemm_mma<<<gD, 256>>>(ahi, alo, bhi, blo, bk, k, Tc, Dc, Dc, 0);
    splitT_kernel<<<Dc * Dc / 256, 256>>>(Wv, bhi, blo, Dc, Dc);
    gemm_mma<<<gD, 256>>>(ahi, alo, bhi, blo, bv, v, Tc, Dc, Dc, 0);

    attn_kernel<<<dim3(Ec / QT2, Bc, 2), 256>>>(q, k, v, sb, mask, be, ao);

    // ---- O projection + LN1 ----
    split2_kernel<<<nX / 4 / 256, 256>>>(ao, ahi, alo, nX / 4);
    splitT_kernel<<<Dc * Dc / 256, 256>>>(Wo, bhi, blo, Dc, Dc);
    gemm_mma<<<gD, 256>>>(ahi, alo, bhi, blo, bo, tmp, Tc, Dc, Dc, 0);
    add_ln_kernel<<<Tc / 8, 256>>>(x, tmp, g1, b1, x1);

    // ---- FFN ----
    split2_kernel<<<nX / 4 / 256, 256>>>(x1, ahi, alo, nX / 4);
    splitT_kernel<<<Dc * 4 * Dc / 256, 256>>>(Wf1, bhi, blo, Dc, 4 * Dc);
    gemm_mma<<<gF1, 256>>>(ahi, alo, bhi, blo, bf1, ff, Tc, 4 * Dc, Dc, 1);
    split2_kernel<<<nFF / 4 / 256, 256>>>(ff, ahi, alo, nFF / 4);
    splitT_kernel<<<4 * Dc * Dc / 256, 256>>>(Wf2, bhi, blo, 4 * Dc, Dc);
    gemm_mma<<<gD, 256>>>(ahi, alo, bhi, blo, bf2, tmp, Tc, Dc, 4 * Dc, 0);
    add_ln_kernel<<<Tc / 8, 256>>>(x1, tmp, g2, b2, out);
}

// round 9
// speedup vs baseline: 1.7974x; 1.1437x over previous
#include <cuda_runtime.h>
#include <cuda_bf16.h>
#include <math.h>

// Problem constants
#define Bc 8
#define Ec 1024
#define Dc 256
#define Hc 16
#define HDc 16
#define Tc (Bc*Ec)          // 8192 tokens
typedef unsigned int u32;

// ---------------- scratch (device globals: allocation-free) ----------------
__device__ float g_x1 [Tc*Dc];
__device__ float g_tmp[Tc*Dc];
// bf16 hi/lo pairs
__device__ __nv_bfloat16 g_xh [Tc*Dc],  g_xl [Tc*Dc];
__device__ __nv_bfloat16 g_qh [Tc*Dc],  g_ql [Tc*Dc];
__device__ __nv_bfloat16 g_kh [Tc*Dc],  g_kl [Tc*Dc];
__device__ __nv_bfloat16 g_vt [Tc*Dc];                 // V transposed per-b: [b][dim][key]
__device__ __nv_bfloat16 g_aoh[Tc*Dc],  g_aol[Tc*Dc];
__device__ __nv_bfloat16 g_x1h[Tc*Dc],  g_x1l[Tc*Dc];
__device__ __nv_bfloat16 g_ffh[Tc*4*Dc], g_ffl[Tc*4*Dc];
__device__ __nv_bfloat16 g_bhi[4*Dc*Dc], g_blo[4*Dc*Dc];  // weight splits (transposed)

// ---------------- helpers ----------------
__device__ __forceinline__ u32 bfpair(float lo, float hi) {
    // returns packed bf16x2: lo -> lower 16 bits, hi -> upper 16 bits
    u32 r;
    asm("cvt.rn.bf16x2.f32 %0, %1, %2;" : "=r"(r) : "f"(hi), "f"(lo));
    return r;
}
__device__ __forceinline__ void bf_hilo2(float a, float b, u32& hp, u32& lp) {
    hp = bfpair(a, b);
    float ha = __int_as_float(hp << 16);
    float hb = __int_as_float(hp & 0xffff0000u);
    lp = bfpair(a - ha, b - hb);
}
__device__ __forceinline__ float gelu_exact(float v) {
    return 0.5f * v * (1.0f + erff(v * 0.7071067811865476f));
}
__device__ __forceinline__ void mma16816(
    float& d0, float& d1, float& d2, float& d3,
    u32 a0, u32 a1, u32 a2, u32 a3, u32 b0, u32 b1)
{
    asm("mma.sync.aligned.m16n8k16.row.col.f32.bf16.bf16.f32 "
        "{%0,%1,%2,%3}, {%4,%5,%6,%7}, {%8,%9}, {%0,%1,%2,%3};"
        : "+f"(d0), "+f"(d1), "+f"(d2), "+f"(d3)
        : "r"(a0), "r"(a1), "r"(a2), "r"(a3), "r"(b0), "r"(b1));
}

// ---------------- fp32 -> bf16 hi/lo split (x input only) ----------------
__global__ __launch_bounds__(256) void split2_kernel(
    const float* __restrict__ in, __nv_bfloat16* __restrict__ hi,
    __nv_bfloat16* __restrict__ lo, int n4)
{
    int i = blockIdx.x * 256 + threadIdx.x;
    if (i >= n4) return;
    float4 f = ((const float4*)in)[i];
    u32 h0, l0, h1, l1;
    bf_hilo2(f.x, f.y, h0, l0);
    bf_hilo2(f.z, f.w, h1, l1);
    ((uint2*)hi)[i] = make_uint2(h0, h1);
    ((uint2*)lo)[i] = make_uint2(l0, l1);
}

// ---------------- weight split + transpose: W[K,N] -> hiT/loT[N,K] ----------------
__global__ __launch_bounds__(256) void splitT_kernel(
    const float* __restrict__ W, __nv_bfloat16* __restrict__ hiT,
    __nv_bfloat16* __restrict__ loT, int K, int N)
{
    int idx = blockIdx.x * 256 + threadIdx.x;
    if (idx >= K * N) return;
    int k = idx / N, n = idx - k * N;
    float f = W[idx];
    __nv_bfloat16 h = __float2bfloat16(f);
    float r = f - __bfloat162float(h);
    hiT[(size_t)n * K + k] = h;
    loT[(size_t)n * K + k] = __float2bfloat16(r);
}

// ---------------- tensor-core GEMM with fused output modes ----------------
// C = A @ B^T + bias; A hi/lo [M,K] bf16, BT hi/lo [N,K] bf16, fp32 accumulate.
// mode 0: fp32 C.  mode 1: bf16 hi/lo C.  mode 2: bf16 Vt [b][row][col&1023].
// biasrow: bias indexed by row instead of col.
#define SAPITCH 24

__global__ __launch_bounds__(256) void gemm_mma(
    const __nv_bfloat16* __restrict__ Ahi, const __nv_bfloat16* __restrict__ Alo,
    const __nv_bfloat16* __restrict__ BhiT, const __nv_bfloat16* __restrict__ BloT,
    const float* __restrict__ bias,
    float* __restrict__ Cf, __nv_bfloat16* __restrict__ Chi, __nv_bfloat16* __restrict__ Clo,
    int M, int N, int K, int act, int mode, int biasrow)
{
    __shared__ __align__(16) __nv_bfloat16 sA[2][128 * SAPITCH];
    __shared__ __align__(16) __nv_bfloat16 sB[2][64 * SAPITCH];

    const int tid  = threadIdx.x;
    const int warp = tid >> 5;
    const int lane = tid & 31;
    const int g    = lane >> 2;
    const int tq   = lane & 3;
    const int wm   = (warp >> 1) * 32;
    const int wn   = (warp & 1) * 32;
    const int m0   = blockIdx.y * 128, n0 = blockIdx.x * 64;

    float acc[2][4][4];
    #pragma unroll
    for (int i = 0; i < 2; i++)
        #pragma unroll
        for (int j = 0; j < 4; j++)
            #pragma unroll
            for (int c = 0; c < 4; c++) acc[i][j][c] = 0.0f;

    const int ar = tid >> 1, akh = (tid & 1) * 8;
    const int bn = tid >> 2, bkq = (tid & 3) * 4;

    for (int k0 = 0; k0 < K; k0 += 16) {
        *(uint4*)&sA[0][ar * SAPITCH + akh] =
            *(const uint4*)(Ahi + (size_t)(m0 + ar) * K + k0 + akh);
        *(uint4*)&sA[1][ar * SAPITCH + akh] =
            *(const uint4*)(Alo + (size_t)(m0 + ar) * K + k0 + akh);
        *(uint2*)&sB[0][bn * SAPITCH + bkq] =
            *(const uint2*)(BhiT + (size_t)(n0 + bn) * K + k0 + bkq);
        *(uint2*)&sB[1][bn * SAPITCH + bkq] =
            *(const uint2*)(BloT + (size_t)(n0 + bn) * K + k0 + bkq);
        __syncthreads();

        u32 afr[2][2][4];
        #pragma unroll
        for (int s = 0; s < 2; s++)
            #pragma unroll
            for (int mt = 0; mt < 2; mt++) {
                int r = wm + mt * 16 + g;
                afr[s][mt][0] = *(const u32*)&sA[s][(r    ) * SAPITCH + tq * 2    ];
                afr[s][mt][1] = *(const u32*)&sA[s][(r + 8) * SAPITCH + tq * 2    ];
                afr[s][mt][2] = *(const u32*)&sA[s][(r    ) * SAPITCH + tq * 2 + 8];
                afr[s][mt][3] = *(const u32*)&sA[s][(r + 8) * SAPITCH + tq * 2 + 8];
            }
        u32 bfr[2][4][2];
        #pragma unroll
        for (int s = 0; s < 2; s++)
            #pragma unroll
            for (int nt = 0; nt < 4; nt++) {
                int r = wn + nt * 8 + g;
                bfr[s][nt][0] = *(const u32*)&sB[s][r * SAPITCH + tq * 2    ];
                bfr[s][nt][1] = *(const u32*)&sB[s][r * SAPITCH + tq * 2 + 8];
            }

        #pragma unroll
        for (int mt = 0; mt < 2; mt++)
            #pragma unroll
            for (int nt = 0; nt < 4; nt++) {
                float* d = acc[mt][nt];
                mma16816(d[0], d[1], d[2], d[3],
                         afr[0][mt][0], afr[0][mt][1], afr[0][mt][2], afr[0][mt][3],
                         bfr[0][nt][0], bfr[0][nt][1]);
                mma16816(d[0], d[1], d[2], d[3],
                         afr[0][mt][0], afr[0][mt][1], afr[0][mt][2], afr[0][mt][3],
                         bfr[1][nt][0], bfr[1][nt][1]);
                mma16816(d[0], d[1], d[2], d[3],
                         afr[1][mt][0], afr[1][mt][1], afr[1][mt][2], afr[1][mt][3],
                         bfr[0][nt][0], bfr[0][nt][1]);
            }
        __syncthreads();
    }

    #pragma unroll
    for (int mt = 0; mt < 2; mt++) {
        int rowA = m0 + wm + mt * 16 + g;
        #pragma unroll
        for (int nt = 0; nt < 4; nt++) {
            int col = n0 + wn + nt * 8 + tq * 2;
            float b0, b1, b2, b3;
            if (biasrow) {
                b0 = b1 = bias[rowA];
                b2 = b3 = bias[rowA + 8];
            } else {
                b0 = b2 = bias[col];
                b1 = b3 = bias[col + 1];
            }
            float* d = acc[mt][nt];
            float o0 = d[0] + b0, o1 = d[1] + b1;
            float o2 = d[2] + b2, o3 = d[3] + b3;
            if (act) {
                o0 = gelu_exact(o0); o1 = gelu_exact(o1);
                o2 = gelu_exact(o2); o3 = gelu_exact(o3);
            }
            if (mode == 0) {
                *(float2*)(Cf + (size_t)rowA * N + col)       = make_float2(o0, o1);
                *(float2*)(Cf + (size_t)(rowA + 8) * N + col) = make_float2(o2, o3);
            } else if (mode == 1) {
                u32 hp, lp;
                bf_hilo2(o0, o1, hp, lp);
                *(u32*)(Chi + (size_t)rowA * N + col) = hp;
                *(u32*)(Clo + (size_t)rowA * N + col) = lp;
                bf_hilo2(o2, o3, hp, lp);
                *(u32*)(Chi + (size_t)(rowA + 8) * N + col) = hp;
                *(u32*)(Clo + (size_t)(rowA + 8) * N + col) = lp;
            } else {
                // Vt: rows are dims, cols are global tokens; [b][dim][tok]
                int bb = col >> 10, tc = col & 1023;
                *(u32*)(Chi + ((size_t)bb * Dc + rowA) * Ec + tc)     = bfpair(o0, o1);
                *(u32*)(Chi + ((size_t)bb * Dc + rowA + 8) * Ec + tc) = bfpair(o2, o3);
            }
        }
    }
}

// ---------------- tensor-core attention ----------------
// Block: 256 thr = 8 warps = 8 heads (group hg); 16 queries per block.
// Warp: 16 queries x all keys for one head. No online max (scores bounded).
#define KP 136   // sK row pitch (bf16 elems): 272B, 16B-aligned, conflict-free frags
#define VP 24    // sVt row pitch: 48B, conflict-free frags

__global__ __launch_bounds__(256, 2) void attn_mma(
    const __nv_bfloat16* __restrict__ Qh, const __nv_bfloat16* __restrict__ Ql,
    const __nv_bfloat16* __restrict__ Kh, const __nv_bfloat16* __restrict__ Kl,
    const __nv_bfloat16* __restrict__ Vt,
    const int* __restrict__ sbias, const unsigned char* __restrict__ mask,
    const float* __restrict__ bias_emb,
    __nv_bfloat16* __restrict__ Ohi, __nv_bfloat16* __restrict__ Olo)
{
    __shared__ __align__(16) __nv_bfloat16 sKh[16 * KP];
    __shared__ __align__(16) __nv_bfloat16 sKl[16 * KP];
    __shared__ __align__(16) __nv_bfloat16 sVt[128 * VP];
    __shared__ int   sSB[16 * 17];
    __shared__ float sBE[8 * 8];
    __shared__ float sM[16];

    const int b    = blockIdx.y;
    const int q0   = blockIdx.x * 16;
    const int hg   = blockIdx.z;
    const int tid  = threadIdx.x;
    const int wid  = tid >> 5;           // local head
    const int lane = tid & 31;
    const int g    = lane >> 2;
    const int tq   = lane & 3;
    const int head = hg * 8 + wid;

    if (tid < 48) {
        int idx = tid >> 3, hh = tid & 7;
        sBE[hh * 8 + idx] = bias_emb[idx * Hc + hg * 8 + hh];
    }

    // Q fragments (hi & lo), loaded once
    u32 aQh[4], aQl[4];
    {
        const __nv_bfloat16* q0p = Qh + ((size_t)(b * Ec + q0 + g)) * Dc + head * HDc;
        const __nv_bfloat16* q8p = q0p + (size_t)8 * Dc;
        aQh[0] = *(const u32*)(q0p + tq * 2);
        aQh[1] = *(const u32*)(q8p + tq * 2);
        aQh[2] = *(const u32*)(q0p + tq * 2 + 8);
        aQh[3] = *(const u32*)(q8p + tq * 2 + 8);
        const __nv_bfloat16* l0p = Ql + ((size_t)(b * Ec + q0 + g)) * Dc + head * HDc;
        const __nv_bfloat16* l8p = l0p + (size_t)8 * Dc;
        aQl[0] = *(const u32*)(l0p + tq * 2);
        aQl[1] = *(const u32*)(l8p + tq * 2);
        aQl[2] = *(const u32*)(l0p + tq * 2 + 8);
        aQl[3] = *(const u32*)(l8p + tq * 2 + 8);
    }

    float oacc[2][4];
    #pragma unroll
    for (int n = 0; n < 2; n++)
        #pragma unroll
        for (int e = 0; e < 4; e++) oacc[n][e] = 0.0f;
    float l0 = 0.0f, l1 = 0.0f;

    const int kr  = tid >> 4, kc8 = (tid & 15) * 8;     // K tile cover
    const int vd  = tid >> 1, vh8 = (tid & 1) * 8;      // Vt tile cover

    for (int k0 = 0; k0 < Ec; k0 += 16) {
        __syncthreads();
        *(uint4*)&sKh[kr * KP + kc8] =
            *(const uint4*)(Kh + ((size_t)(b * Ec + k0 + kr)) * Dc + hg * 128 + kc8);
        *(uint4*)&sKl[kr * KP + kc8] =
            *(const uint4*)(Kl + ((size_t)(b * Ec + k0 + kr)) * Dc + hg * 128 + kc8);
        *(uint4*)&sVt[vd * VP + vh8] =
            *(const uint4*)(Vt + ((size_t)b * Dc + hg * 128 + vd) * Ec + k0 + vh8);
        sSB[(tid >> 4) * 17 + (tid & 15)] =
            sbias[(size_t)b * Ec * Ec + (size_t)(q0 + (tid >> 4)) * Ec + k0 + (tid & 15)];
        if (tid < 16) sM[tid] = mask[b * Ec + k0 + tid] ? -1e30f : 0.0f;
        __syncthreads();

        // ---- scores: two 16x8 tiles, Q/K hi-lo split ----
        float c[2][4];
        #pragma unroll
        for (int t = 0; t < 2; t++) {
            c[t][0] = c[t][1] = c[t][2] = c[t][3] = 0.0f;
            int krow = (t * 8 + g) * KP + wid * HDc;
            u32 bh0 = *(const u32*)&sKh[krow + tq * 2];
            u32 bh1 = *(const u32*)&sKh[krow + tq * 2 + 8];
            u32 bl0 = *(const u32*)&sKl[krow + tq * 2];
            u32 bl1 = *(const u32*)&sKl[krow + tq * 2 + 8];
            mma16816(c[t][0], c[t][1], c[t][2], c[t][3],
                     aQh[0], aQh[1], aQh[2], aQh[3], bh0, bh1);
            mma16816(c[t][0], c[t][1], c[t][2], c[t][3],
                     aQh[0], aQh[1], aQh[2], aQh[3], bl0, bl1);
            mma16816(c[t][0], c[t][1], c[t][2], c[t][3],
                     aQl[0], aQl[1], aQl[2], aQl[3], bh0, bh1);
        }

        // ---- softmax terms ----
        float m00 = sM[tq * 2], m01 = sM[tq * 2 + 1];
        float m10 = sM[tq * 2 + 8], m11 = sM[tq * 2 + 9];
        const int* sr0 = &sSB[g * 17];
        const int* sr8 = &sSB[(g + 8) * 17];
        const float* be = &sBE[wid * 8];
        float p[2][4];
        #pragma unroll
        for (int t = 0; t < 2; t++) {
            int kc = t * 8 + tq * 2;
            float e0 = __expf(fmaf(c[t][0], 0.25f, be[sr0[kc]]     + (t ? m10 : m00)));
            float e1 = __expf(fmaf(c[t][1], 0.25f, be[sr0[kc + 1]] + (t ? m11 : m01)));
            float e2 = __expf(fmaf(c[t][2], 0.25f, be[sr8[kc]]     + (t ? m10 : m00)));
            float e3 = __expf(fmaf(c[t][3], 0.25f, be[sr8[kc + 1]] + (t ? m11 : m01)));
            l0 += e0 + e1;
            l1 += e2 + e3;
            p[t][0] = e0; p[t][1] = e1; p[t][2] = e2; p[t][3] = e3;
        }

        // ---- P fragment (bf16) + PV mmas ----
        u32 pA0 = bfpair(p[0][0], p[0][1]);
        u32 pA1 = bfpair(p[0][2], p[0][3]);
        u32 pA2 = bfpair(p[1][0], p[1][1]);
        u32 pA3 = bfpair(p[1][2], p[1][3]);
        #pragma unroll
        for (int n = 0; n < 2; n++) {
            int vrow = (wid * HDc + n * 8 + g) * VP;
            u32 bv0 = *(const u32*)&sVt[vrow + tq * 2];
            u32 bv1 = *(const u32*)&sVt[vrow + tq * 2 + 8];
            mma16816(oacc[n][0], oacc[n][1], oacc[n][2], oacc[n][3],
                     pA0, pA1, pA2, pA3, bv0, bv1);
        }
    }

    // row-sum reduce l over the quad (lanes g*4..g*4+3)
    l0 += __shfl_xor_sync(0xFFFFFFFFu, l0, 1);
    l0 += __shfl_xor_sync(0xFFFFFFFFu, l0, 2);
    l1 += __shfl_xor_sync(0xFFFFFFFFu, l1, 1);
    l1 += __shfl_xor_sync(0xFFFFFFFFu, l1, 2);
    float i0 = 1.0f / l0, i1 = 1.0f / l1;

    #pragma unroll
    for (int n = 0; n < 2; n++) {
        size_t r0 = ((size_t)(b * Ec + q0 + g)) * Dc + head * HDc + n * 8 + tq * 2;
        size_t r8 = r0 + (size_t)8 * Dc;
        u32 hp, lp;
        bf_hilo2(oacc[n][0] * i0, oacc[n][1] * i0, hp, lp);
        *(u32*)(Ohi + r0) = hp;
        *(u32*)(Olo + r0) = lp;
        bf_hilo2(oacc[n][2] * i1, oacc[n][3] * i1, hp, lp);
        *(u32*)(Ohi + r8) = hp;
        *(u32*)(Olo + r8) = lp;
    }
}

// ---------------- residual add + layernorm (+ optional bf16 hi/lo out) ----------------
__global__ __launch_bounds__(256) void add_ln_kernel(
    const float* __restrict__ x, const float* __restrict__ y,
    const float* __restrict__ g, const float* __restrict__ b,
    float* __restrict__ out,
    __nv_bfloat16* __restrict__ ohi, __nv_bfloat16* __restrict__ olo)
{
    const int row  = blockIdx.x * 8 + (threadIdx.x >> 5);
    const int lane = threadIdx.x & 31;
    const float* xr = x + (size_t)row * Dc;
    const float* yr = y + (size_t)row * Dc;

    float v[8];
    float s = 0.0f, s2 = 0.0f;
    #pragma unroll
    for (int i = 0; i < 8; i++) {
        float t = xr[i * 32 + lane] + yr[i * 32 + lane];
        v[i] = t;
        s += t;
        s2 = fmaf(t, t, s2);
    }
    #pragma unroll
    for (int o = 16; o > 0; o >>= 1) {
        s  += __shfl_xor_sync(0xFFFFFFFFu, s,  o);
        s2 += __shfl_xor_sync(0xFFFFFFFFu, s2, o);
    }
    float mu  = s * (1.0f / 256.0f);
    float var = s2 * (1.0f / 256.0f) - mu * mu;
    float r   = rsqrtf(var + 1e-5f);
    #pragma unroll
    for (int i = 0; i < 8; i++) {
        int c = i * 32 + lane;
        float o = (v[i] - mu) * r * g[c] + b[c];
        out[(size_t)row * Dc + c] = o;
        if (ohi) {
            __nv_bfloat16 h = __float2bfloat16(o);
            ohi[(size_t)row * Dc + c] = h;
            olo[(size_t)row * Dc + c] = __float2bfloat16(o - __bfloat162float(h));
        }
    }
}

// ---------------- launch ----------------
extern "C" void kernel_launch(void* const* d_in, const int* in_sizes, int n_in,
                              void* d_out, int out_size)
{
    const float* x    = (const float*)d_in[0];
    const int*   sb   = (const int*)d_in[1];
    const unsigned char* mask = (const unsigned char*)d_in[2];
    const float* Wq = (const float*)d_in[3];  const float* bq = (const float*)d_in[4];
    const float* Wk = (const float*)d_in[5];  const float* bk = (const float*)d_in[6];
    const float* Wv = (const float*)d_in[7];  const float* bv = (const float*)d_in[8];
    const float* Wo = (const float*)d_in[9];  const float* bo = (const float*)d_in[10];
    const float* be = (const float*)d_in[11];
    const float* g1 = (const float*)d_in[12]; const float* b1 = (const float*)d_in[13];
    const float* Wf1 = (const float*)d_in[14]; const float* bf1 = (const float*)d_in[15];
    const float* Wf2 = (const float*)d_in[16]; const float* bf2 = (const float*)d_in[17];
    const float* g2 = (const float*)d_in[18]; const float* b2 = (const float*)d_in[19];
    float* out = (float*)d_out;

    float *x1, *tmp;
    __nv_bfloat16 *xh, *xl, *qh, *ql, *kh, *kl, *vt, *aoh, *aol, *x1h, *x1l, *ffh, *ffl, *bhi, *blo;
    cudaGetSymbolAddress((void**)&x1,  g_x1);
    cudaGetSymbolAddress((void**)&tmp, g_tmp);
    cudaGetSymbolAddress((void**)&xh,  g_xh);  cudaGetSymbolAddress((void**)&xl,  g_xl);
    cudaGetSymbolAddress((void**)&qh,  g_qh);  cudaGetSymbolAddress((void**)&ql,  g_ql);
    cudaGetSymbolAddress((void**)&kh,  g_kh);  cudaGetSymbolAddress((void**)&kl,  g_kl);
    cudaGetSymbolAddress((void**)&vt,  g_vt);
    cudaGetSymbolAddress((void**)&aoh, g_aoh); cudaGetSymbolAddress((void**)&aol, g_aol);
    cudaGetSymbolAddress((void**)&x1h, g_x1h); cudaGetSymbolAddress((void**)&x1l, g_x1l);
    cudaGetSymbolAddress((void**)&ffh, g_ffh); cudaGetSymbolAddress((void**)&ffl, g_ffl);
    cudaGetSymbolAddress((void**)&bhi, g_bhi); cudaGetSymbolAddress((void**)&blo, g_blo);

    const int nX = Tc * Dc;
    dim3 gD (Dc / 64,     Tc / 128);   // (4, 64)   [M=8192, N=256]
    dim3 gF1(4 * Dc / 64, Tc / 128);   // (16, 64)  [M=8192, N=1024]
    dim3 gVt(Tc / 64,     Dc / 128);   // (128, 2)  [M=256,  N=8192]

    // x split (feeds Q,K,V gemms)
    split2_kernel<<<nX / 4 / 256, 256>>>(x, xh, xl, nX / 4);

    // Q, K projections -> bf16 hi/lo
    splitT_kernel<<<Dc * Dc / 256, 256>>>(Wq, bhi, blo, Dc, Dc);
    gemm_mma<<<gD, 256>>>(xh, xl, bhi, blo, bq, nullptr, qh, ql, Tc, Dc, Dc, 0, 1, 0);
    splitT_kernel<<<Dc * Dc / 256, 256>>>(Wk, bhi, blo, Dc, Dc);
    gemm_mma<<<gD, 256>>>(xh, xl, bhi, blo, bk, nullptr, kh, kl, Tc, Dc, Dc, 0, 1, 0);
    // V projection transposed: Vt = Wv^T @ x^T  (A = WvT, BT = x), bias per-row
    splitT_kernel<<<Dc * Dc / 256, 256>>>(Wv, bhi, blo, Dc, Dc);
    gemm_mma<<<gVt, 256>>>(bhi, blo, xh, xl, bv, nullptr, vt, nullptr, Dc, Tc, Dc, 0, 2, 1);

    // attention (tensor cores) -> ao bf16 hi/lo
    attn_mma<<<dim3(Ec / 16, Bc, 2), 256>>>(qh, ql, kh, kl, vt, sb, mask, be, aoh, aol);

    // O projection -> fp32 tmp; LN1 -> x1 fp32 + hi/lo
    splitT_kernel<<<Dc * Dc / 256, 256>>>(Wo, bhi, blo, Dc, Dc);
    gemm_mma<<<gD, 256>>>(aoh, aol, bhi, blo, bo, tmp, nullptr, nullptr, Tc, Dc, Dc, 0, 0, 0);
    add_ln_kernel<<<Tc / 8, 256>>>(x, tmp, g1, b1, x1, x1h, x1l);

    // FFN
    splitT_kernel<<<Dc * 4 * Dc / 256, 256>>>(Wf1, bhi, blo, Dc, 4 * Dc);
    gemm_mma<<<gF1, 256>>>(x1h, x1l, bhi, blo, bf1, nullptr, ffh, ffl, Tc, 4 * Dc, Dc, 1, 1, 0);
    splitT_kernel<<<4 * Dc * Dc / 256, 256>>>(Wf2, bhi, blo, 4 * Dc, Dc);
    gemm_mma<<<gD, 256>>>(ffh, ffl, bhi, blo, bf2, tmp, nullptr, nullptr, Tc, Dc, 4 * Dc, 0, 0, 0);
    add_ln_kernel<<<Tc / 8, 256>>>(x1, tmp, g2, b2, out, nullptr, nullptr);
}

// round 11
// speedup vs baseline: 2.0276x; 1.1281x over previous
#include <cuda_runtime.h>
#include <cuda_bf16.h>
#include <math.h>

// Problem constants
#define Bc 8
#define Ec 1024
#define Dc 256
#define Hc 16
#define HDc 16
#define Tc (Bc*Ec)          // 8192 tokens
typedef unsigned int u32;

// ---------------- scratch (device globals: allocation-free) ----------------
__device__ float g_x1 [Tc*Dc];
__device__ float g_tmp[Tc*Dc];
__device__ __nv_bfloat16 g_xh [Tc*Dc],  g_xl [Tc*Dc];
__device__ __nv_bfloat16 g_qh [Tc*Dc],  g_ql [Tc*Dc];
__device__ __nv_bfloat16 g_kh [Tc*Dc],  g_kl [Tc*Dc];
__device__ __nv_bfloat16 g_vt [Tc*Dc];                 // V transposed per-b: [b][dim][key]
__device__ __nv_bfloat16 g_aoh[Tc*Dc],  g_aol[Tc*Dc];
__device__ __nv_bfloat16 g_x1h[Tc*Dc],  g_x1l[Tc*Dc];
__device__ __nv_bfloat16 g_ffh[Tc*4*Dc], g_ffl[Tc*4*Dc];
// per-weight splits (transposed [N,K])
__device__ __nv_bfloat16 g_wqh[Dc*Dc],   g_wql[Dc*Dc];
__device__ __nv_bfloat16 g_wkh[Dc*Dc],   g_wkl[Dc*Dc];
__device__ __nv_bfloat16 g_wvh[Dc*Dc],   g_wvl[Dc*Dc];
__device__ __nv_bfloat16 g_woh[Dc*Dc],   g_wol[Dc*Dc];
__device__ __nv_bfloat16 g_wf1h[Dc*4*Dc], g_wf1l[Dc*4*Dc];
__device__ __nv_bfloat16 g_wf2h[4*Dc*Dc], g_wf2l[4*Dc*Dc];

// ---------------- helpers ----------------
__device__ __forceinline__ u32 bfpair(float lo, float hi) {
    u32 r;
    asm("cvt.rn.bf16x2.f32 %0, %1, %2;" : "=r"(r) : "f"(hi), "f"(lo));
    return r;
}
__device__ __forceinline__ void bf_hilo2(float a, float b, u32& hp, u32& lp) {
    hp = bfpair(a, b);
    float ha = __int_as_float(hp << 16);
    float hb = __int_as_float(hp & 0xffff0000u);
    lp = bfpair(a - ha, b - hb);
}
__device__ __forceinline__ float gelu_exact(float v) {
    return 0.5f * v * (1.0f + erff(v * 0.7071067811865476f));
}
__device__ __forceinline__ void mma16816(
    float& d0, float& d1, float& d2, float& d3,
    u32 a0, u32 a1, u32 a2, u32 a3, u32 b0, u32 b1)
{
    asm("mma.sync.aligned.m16n8k16.row.col.f32.bf16.bf16.f32 "
        "{%0,%1,%2,%3}, {%4,%5,%6,%7}, {%8,%9}, {%0,%1,%2,%3};"
        : "+f"(d0), "+f"(d1), "+f"(d2), "+f"(d3)
        : "r"(a0), "r"(a1), "r"(a2), "r"(a3), "r"(b0), "r"(b1));
}
__device__ __forceinline__ void cpa16(u32 dst, const void* src) {
    asm volatile("cp.async.ca.shared.global [%0], [%1], 16;" :: "r"(dst), "l"(src));
}
__device__ __forceinline__ void cpa8(u32 dst, const void* src) {
    asm volatile("cp.async.ca.shared.global [%0], [%1], 8;" :: "r"(dst), "l"(src));
}

// ---------------- fp32 -> bf16 hi/lo split (x input only) ----------------
__global__ __launch_bounds__(256) void split2_kernel(
    const float* __restrict__ in, __nv_bfloat16* __restrict__ hi,
    __nv_bfloat16* __restrict__ lo, int n4)
{
    int i = blockIdx.x * 256 + threadIdx.x;
    if (i >= n4) return;
    float4 f = ((const float4*)in)[i];
    u32 h0, l0, h1, l1;
    bf_hilo2(f.x, f.y, h0, l0);
    bf_hilo2(f.z, f.w, h1, l1);
    ((uint2*)hi)[i] = make_uint2(h0, h1);
    ((uint2*)lo)[i] = make_uint2(l0, l1);
}

// ---------------- all weight splits (one kernel): W[K,N] -> hiT/loT[N,K] ----------------
__global__ __launch_bounds__(256) void splitW_all(
    const float* __restrict__ Wq, const float* __restrict__ Wk,
    const float* __restrict__ Wv, const float* __restrict__ Wo,
    const float* __restrict__ Wf1, const float* __restrict__ Wf2,
    __nv_bfloat16* __restrict__ qh, __nv_bfloat16* __restrict__ ql,
    __nv_bfloat16* __restrict__ kh, __nv_bfloat16* __restrict__ kl,
    __nv_bfloat16* __restrict__ vh, __nv_bfloat16* __restrict__ vl,
    __nv_bfloat16* __restrict__ oh, __nv_bfloat16* __restrict__ ol,
    __nv_bfloat16* __restrict__ f1h, __nv_bfloat16* __restrict__ f1l,
    __nv_bfloat16* __restrict__ f2h, __nv_bfloat16* __restrict__ f2l)
{
    int bid = blockIdx.x;
    const float* W;
    __nv_bfloat16 *hiT, *loT;
    int K, N, idx;
    if (bid < 1024) {
        int m = bid >> 8;                    // which of Wq/Wk/Wv/Wo
        K = Dc; N = Dc;
        idx = (bid & 255) * 256 + threadIdx.x;
        if      (m == 0) { W = Wq; hiT = qh; loT = ql; }
        else if (m == 1) { W = Wk; hiT = kh; loT = kl; }
        else if (m == 2) { W = Wv; hiT = vh; loT = vl; }
        else             { W = Wo; hiT = oh; loT = ol; }
    } else if (bid < 2048) {
        K = Dc; N = 4 * Dc;
        idx = (bid - 1024) * 256 + threadIdx.x;
        W = Wf1; hiT = f1h; loT = f1l;
    } else {
        K = 4 * Dc; N = Dc;
        idx = (bid - 2048) * 256 + threadIdx.x;
        W = Wf2; hiT = f2h; loT = f2l;
    }
    int k = idx / N, n = idx - k * N;
    float f = W[idx];
    __nv_bfloat16 h = __float2bfloat16(f);
    float r = f - __bfloat162float(h);
    hiT[(size_t)n * K + k] = h;
    loT[(size_t)n * K + k] = __float2bfloat16(r);
}

// ---------------- tensor-core GEMM, cp.async double-buffered ----------------
// C = A @ B^T + bias; A hi/lo [M,K] bf16, BT hi/lo [N,K] bf16, fp32 accumulate.
// mode 0: fp32 C.  mode 1: bf16 hi/lo C.  mode 2: bf16 Vt [b][row][tok].
#define SAPITCH 24

__global__ __launch_bounds__(256) void gemm_mma(
    const __nv_bfloat16* __restrict__ Ahi, const __nv_bfloat16* __restrict__ Alo,
    const __nv_bfloat16* __restrict__ BhiT, const __nv_bfloat16* __restrict__ BloT,
    const float* __restrict__ bias,
    float* __restrict__ Cf, __nv_bfloat16* __restrict__ Chi, __nv_bfloat16* __restrict__ Clo,
    int M, int N, int K, int act, int mode, int biasrow)
{
    __shared__ __align__(16) __nv_bfloat16 sA[2][2][128 * SAPITCH];  // [stage][split]
    __shared__ __align__(16) __nv_bfloat16 sB[2][2][64 * SAPITCH];

    const int tid  = threadIdx.x;
    const int warp = tid >> 5;
    const int lane = tid & 31;
    const int g    = lane >> 2;
    const int tq   = lane & 3;
    const int wm   = (warp >> 1) * 32;
    const int wn   = (warp & 1) * 32;
    const int m0   = blockIdx.y * 128, n0 = blockIdx.x * 64;

    float acc[2][4][4];
    #pragma unroll
    for (int i = 0; i < 2; i++)
        #pragma unroll
        for (int j = 0; j < 4; j++)
            #pragma unroll
            for (int c = 0; c < 4; c++) acc[i][j][c] = 0.0f;

    const int ar = tid >> 1, akh = (tid & 1) * 8;
    const int bn = tid >> 2, bkq = (tid & 3) * 4;

    u32 dA0[2], dA1[2], dB0[2], dB1[2];
    #pragma unroll
    for (int st = 0; st < 2; st++) {
        dA0[st] = (u32)__cvta_generic_to_shared(&sA[st][0][ar * SAPITCH + akh]);
        dA1[st] = (u32)__cvta_generic_to_shared(&sA[st][1][ar * SAPITCH + akh]);
        dB0[st] = (u32)__cvta_generic_to_shared(&sB[st][0][bn * SAPITCH + bkq]);
        dB1[st] = (u32)__cvta_generic_to_shared(&sB[st][1][bn * SAPITCH + bkq]);
    }

    // prologue: prefetch k0 = 0 into stage 0
    cpa16(dA0[0], Ahi + (size_t)(m0 + ar) * K + akh);
    cpa16(dA1[0], Alo + (size_t)(m0 + ar) * K + akh);
    cpa8 (dB0[0], BhiT + (size_t)(n0 + bn) * K + bkq);
    cpa8 (dB1[0], BloT + (size_t)(n0 + bn) * K + bkq);
    asm volatile("cp.async.commit_group;");

    int stage = 0;
    for (int k0 = 0; k0 < K; k0 += 16) {
        asm volatile("cp.async.wait_group 0;" ::: "memory");
        __syncthreads();
        if (k0 + 16 < K) {
            int st = stage ^ 1, kn = k0 + 16;
            cpa16(dA0[st], Ahi + (size_t)(m0 + ar) * K + kn + akh);
            cpa16(dA1[st], Alo + (size_t)(m0 + ar) * K + kn + akh);
            cpa8 (dB0[st], BhiT + (size_t)(n0 + bn) * K + kn + bkq);
            cpa8 (dB1[st], BloT + (size_t)(n0 + bn) * K + kn + bkq);
            asm volatile("cp.async.commit_group;");
        }

        u32 afr[2][2][4];
        #pragma unroll
        for (int s = 0; s < 2; s++)
            #pragma unroll
            for (int mt = 0; mt < 2; mt++) {
                int r = wm + mt * 16 + g;
                afr[s][mt][0] = *(const u32*)&sA[stage][s][(r    ) * SAPITCH + tq * 2    ];
                afr[s][mt][1] = *(const u32*)&sA[stage][s][(r + 8) * SAPITCH + tq * 2    ];
                afr[s][mt][2] = *(const u32*)&sA[stage][s][(r    ) * SAPITCH + tq * 2 + 8];
                afr[s][mt][3] = *(const u32*)&sA[stage][s][(r + 8) * SAPITCH + tq * 2 + 8];
            }
        u32 bfr[2][4][2];
        #pragma unroll
        for (int s = 0; s < 2; s++)
            #pragma unroll
            for (int nt = 0; nt < 4; nt++) {
                int r = wn + nt * 8 + g;
                bfr[s][nt][0] = *(const u32*)&sB[stage][s][r * SAPITCH + tq * 2    ];
                bfr[s][nt][1] = *(const u32*)&sB[stage][s][r * SAPITCH + tq * 2 + 8];
            }

        #pragma unroll
        for (int mt = 0; mt < 2; mt++)
            #pragma unroll
            for (int nt = 0; nt < 4; nt++) {
                float* d = acc[mt][nt];
                mma16816(d[0], d[1], d[2], d[3],
                         afr[0][mt][0], afr[0][mt][1], afr[0][mt][2], afr[0][mt][3],
                         bfr[0][nt][0], bfr[0][nt][1]);
                mma16816(d[0], d[1], d[2], d[3],
                         afr[0][mt][0], afr[0][mt][1], afr[0][mt][2], afr[0][mt][3],
                         bfr[1][nt][0], bfr[1][nt][1]);
                mma16816(d[0], d[1], d[2], d[3],
                         afr[1][mt][0], afr[1][mt][1], afr[1][mt][2], afr[1][mt][3],
                         bfr[0][nt][0], bfr[0][nt][1]);
            }
        stage ^= 1;
    }

    #pragma unroll
    for (int mt = 0; mt < 2; mt++) {
        int rowA = m0 + wm + mt * 16 + g;
        #pragma unroll
        for (int nt = 0; nt < 4; nt++) {
            int col = n0 + wn + nt * 8 + tq * 2;
            float b0, b1, b2, b3;
            if (biasrow) {
                b0 = b1 = bias[rowA];
                b2 = b3 = bias[rowA + 8];
            } else {
                b0 = b2 = bias[col];
                b1 = b3 = bias[col + 1];
            }
            float* d = acc[mt][nt];
            float o0 = d[0] + b0, o1 = d[1] + b1;
            float o2 = d[2] + b2, o3 = d[3] + b3;
            if (act) {
                o0 = gelu_exact(o0); o1 = gelu_exact(o1);
                o2 = gelu_exact(o2); o3 = gelu_exact(o3);
            }
            if (mode == 0) {
                *(float2*)(Cf + (size_t)rowA * N + col)       = make_float2(o0, o1);
                *(float2*)(Cf + (size_t)(rowA + 8) * N + col) = make_float2(o2, o3);
            } else if (mode == 1) {
                u32 hp, lp;
                bf_hilo2(o0, o1, hp, lp);
                *(u32*)(Chi + (size_t)rowA * N + col) = hp;
                *(u32*)(Clo + (size_t)rowA * N + col) = lp;
                bf_hilo2(o2, o3, hp, lp);
                *(u32*)(Chi + (size_t)(rowA + 8) * N + col) = hp;
                *(u32*)(Clo + (size_t)(rowA + 8) * N + col) = lp;
            } else {
                int bb = col >> 10, tc = col & 1023;
                *(u32*)(Chi + ((size_t)bb * Dc + rowA) * Ec + tc)     = bfpair(o0, o1);
                *(u32*)(Chi + ((size_t)bb * Dc + rowA + 8) * Ec + tc) = bfpair(o2, o3);
            }
        }
    }
}

// ---------------- tensor-core attention: 32 q/block, 32 keys/tile ----------------
#define KP 136   // sK row pitch (bf16): 128 dims + 8 pad
#define VP 40    // sVt row pitch (bf16): 32 keys + 8 pad

__global__ __launch_bounds__(256, 2) void attn_mma(
    const __nv_bfloat16* __restrict__ Qh, const __nv_bfloat16* __restrict__ Ql,
    const __nv_bfloat16* __restrict__ Kh, const __nv_bfloat16* __restrict__ Kl,
    const __nv_bfloat16* __restrict__ Vt,
    const int* __restrict__ sbias, const unsigned char* __restrict__ mask,
    const float* __restrict__ bias_emb,
    __nv_bfloat16* __restrict__ Ohi, __nv_bfloat16* __restrict__ Olo)
{
    __shared__ __align__(16) __nv_bfloat16 sKh[32 * KP];
    __shared__ __align__(16) __nv_bfloat16 sKl[32 * KP];
    __shared__ __align__(16) __nv_bfloat16 sVt[128 * VP];
    __shared__ int   sSB[32 * 33];
    __shared__ float sBE[8 * 8];
    __shared__ float sM[32];

    const int b    = blockIdx.y;
    const int q0   = blockIdx.x * 32;
    const int hg   = blockIdx.z;
    const int tid  = threadIdx.x;
    const int wid  = tid >> 5;
    const int lane = tid & 31;
    const int g    = lane >> 2;
    const int tq   = lane & 3;
    const int head = hg * 8 + wid;

    if (tid < 48) {
        int idx = tid >> 3, hh = tid & 7;
        sBE[hh * 8 + idx] = bias_emb[idx * Hc + hg * 8 + hh];
    }

    // Q fragments: 2 q-tiles x (hi,lo) x 4 regs
    u32 aQh[2][4], aQl[2][4];
    #pragma unroll
    for (int qt = 0; qt < 2; qt++) {
        const __nv_bfloat16* q0p = Qh + ((size_t)(b * Ec + q0 + qt * 16 + g)) * Dc + head * HDc;
        const __nv_bfloat16* q8p = q0p + (size_t)8 * Dc;
        aQh[qt][0] = *(const u32*)(q0p + tq * 2);
        aQh[qt][1] = *(const u32*)(q8p + tq * 2);
        aQh[qt][2] = *(const u32*)(q0p + tq * 2 + 8);
        aQh[qt][3] = *(const u32*)(q8p + tq * 2 + 8);
        const __nv_bfloat16* l0p = Ql + ((size_t)(b * Ec + q0 + qt * 16 + g)) * Dc + head * HDc;
        const __nv_bfloat16* l8p = l0p + (size_t)8 * Dc;
        aQl[qt][0] = *(const u32*)(l0p + tq * 2);
        aQl[qt][1] = *(const u32*)(l8p + tq * 2);
        aQl[qt][2] = *(const u32*)(l0p + tq * 2 + 8);
        aQl[qt][3] = *(const u32*)(l8p + tq * 2 + 8);
    }

    float oacc[2][2][4];
    #pragma unroll
    for (int qt = 0; qt < 2; qt++)
        #pragma unroll
        for (int n = 0; n < 2; n++)
            #pragma unroll
            for (int e = 0; e < 4; e++) oacc[qt][n][e] = 0.0f;
    float lsum[2][2] = {};

    const int kr  = tid >> 4,  kc8 = (tid & 15) * 8;    // K tile: idx and idx+256
    const int vd  = tid >> 2,  vk8 = (tid & 3) * 8;     // Vt tile
    const int sbr = tid >> 3,  sbc = (tid & 7) * 4;     // SB tile

    for (int k0 = 0; k0 < Ec; k0 += 32) {
        __syncthreads();
        {
            const __nv_bfloat16* Kg = Kh + ((size_t)(b * Ec + k0)) * Dc + hg * 128;
            const __nv_bfloat16* Lg = Kl + ((size_t)(b * Ec + k0)) * Dc + hg * 128;
            *(uint4*)&sKh[kr * KP + kc8]        = *(const uint4*)(Kg + (size_t)kr * Dc + kc8);
            *(uint4*)&sKh[(kr + 16) * KP + kc8] = *(const uint4*)(Kg + (size_t)(kr + 16) * Dc + kc8);
            *(uint4*)&sKl[kr * KP + kc8]        = *(const uint4*)(Lg + (size_t)kr * Dc + kc8);
            *(uint4*)&sKl[(kr + 16) * KP + kc8] = *(const uint4*)(Lg + (size_t)(kr + 16) * Dc + kc8);
            const __nv_bfloat16* Vg = Vt + ((size_t)b * Dc + hg * 128) * Ec + k0;
            *(uint4*)&sVt[vd * VP + vk8]        = *(const uint4*)(Vg + (size_t)vd * Ec + vk8);
            *(uint4*)&sVt[(vd + 64) * VP + vk8] = *(const uint4*)(Vg + (size_t)(vd + 64) * Ec + vk8);
            int4 t = *(const int4*)(sbias + (size_t)b * Ec * Ec + (size_t)(q0 + sbr) * Ec + k0 + sbc);
            int* d = &sSB[sbr * 33 + sbc];
            d[0] = t.x; d[1] = t.y; d[2] = t.z; d[3] = t.w;
            if (tid < 32) sM[tid] = mask[b * Ec + k0 + tid] ? -1e30f : 0.0f;
        }
        __syncthreads();

        // ---- scores: 2 q-tiles x 4 key-tiles, hi/lo split (3 mma) ----
        float c[2][4][4];
        #pragma unroll
        for (int nt = 0; nt < 4; nt++) {
            int krow = (nt * 8 + g) * KP + wid * HDc;
            u32 bh0 = *(const u32*)&sKh[krow + tq * 2];
            u32 bh1 = *(const u32*)&sKh[krow + tq * 2 + 8];
            u32 bl0 = *(const u32*)&sKl[krow + tq * 2];
            u32 bl1 = *(const u32*)&sKl[krow + tq * 2 + 8];
            #pragma unroll
            for (int qt = 0; qt < 2; qt++) {
                float* d = c[qt][nt];
                d[0] = d[1] = d[2] = d[3] = 0.0f;
                mma16816(d[0], d[1], d[2], d[3],
                         aQh[qt][0], aQh[qt][1], aQh[qt][2], aQh[qt][3], bh0, bh1);
                mma16816(d[0], d[1], d[2], d[3],
                         aQh[qt][0], aQh[qt][1], aQh[qt][2], aQh[qt][3], bl0, bl1);
                mma16816(d[0], d[1], d[2], d[3],
                         aQl[qt][0], aQl[qt][1], aQl[qt][2], aQl[qt][3], bh0, bh1);
            }
        }

        // ---- softmax + PV per q-tile ----
        #pragma unroll
        for (int qt = 0; qt < 2; qt++) {
            const int* sr0 = &sSB[(qt * 16 + g) * 33];
            const int* sr8 = &sSB[(qt * 16 + g + 8) * 33];
            const float* be = &sBE[wid * 8];
            float p[4][4];
            #pragma unroll
            for (int nt = 0; nt < 4; nt++) {
                int kc = nt * 8 + tq * 2;
                float m0v = sM[kc], m1v = sM[kc + 1];
                float e0 = __expf(fmaf(c[qt][nt][0], 0.25f, be[sr0[kc]]     + m0v));
                float e1 = __expf(fmaf(c[qt][nt][1], 0.25f, be[sr0[kc + 1]] + m1v));
                float e2 = __expf(fmaf(c[qt][nt][2], 0.25f, be[sr8[kc]]     + m0v));
                float e3 = __expf(fmaf(c[qt][nt][3], 0.25f, be[sr8[kc + 1]] + m1v));
                lsum[qt][0] += e0 + e1;
                lsum[qt][1] += e2 + e3;
                p[nt][0] = e0; p[nt][1] = e1; p[nt][2] = e2; p[nt][3] = e3;
            }
            u32 pa[2][4];
            #pragma unroll
            for (int ch = 0; ch < 2; ch++) {
                pa[ch][0] = bfpair(p[2*ch][0],   p[2*ch][1]);
                pa[ch][1] = bfpair(p[2*ch][2],   p[2*ch][3]);
                pa[ch][2] = bfpair(p[2*ch+1][0], p[2*ch+1][1]);
                pa[ch][3] = bfpair(p[2*ch+1][2], p[2*ch+1][3]);
            }
            #pragma unroll
            for (int n = 0; n < 2; n++) {
                int vrow = (wid * HDc + n * 8 + g) * VP;
                #pragma unroll
                for (int ch = 0; ch < 2; ch++) {
                    u32 bv0 = *(const u32*)&sVt[vrow + ch * 16 + tq * 2];
                    u32 bv1 = *(const u32*)&sVt[vrow + ch * 16 + tq * 2 + 8];
                    mma16816(oacc[qt][n][0], oacc[qt][n][1], oacc[qt][n][2], oacc[qt][n][3],
                             pa[ch][0], pa[ch][1], pa[ch][2], pa[ch][3], bv0, bv1);
                }
            }
        }
    }

    #pragma unroll
    for (int qt = 0; qt < 2; qt++) {
        float l0 = lsum[qt][0], l1 = lsum[qt][1];
        l0 += __shfl_xor_sync(0xFFFFFFFFu, l0, 1);
        l0 += __shfl_xor_sync(0xFFFFFFFFu, l0, 2);
        l1 += __shfl_xor_sync(0xFFFFFFFFu, l1, 1);
        l1 += __shfl_xor_sync(0xFFFFFFFFu, l1, 2);
        float i0 = 1.0f / l0, i1 = 1.0f / l1;
        #pragma unroll
        for (int n = 0; n < 2; n++) {
            size_t r0 = ((size_t)(b * Ec + q0 + qt * 16 + g)) * Dc + head * HDc + n * 8 + tq * 2;
            size_t r8 = r0 + (size_t)8 * Dc;
            u32 hp, lp;
            bf_hilo2(oacc[qt][n][0] * i0, oacc[qt][n][1] * i0, hp, lp);
            *(u32*)(Ohi + r0) = hp;
            *(u32*)(Olo + r0) = lp;
            bf_hilo2(oacc[qt][n][2] * i1, oacc[qt][n][3] * i1, hp, lp);
            *(u32*)(Ohi + r8) = hp;
            *(u32*)(Olo + r8) = lp;
        }
    }
}

// ---------------- residual add + layernorm (+ optional bf16 hi/lo out) ----------------
__global__ __launch_bounds__(256) void add_ln_kernel(
    const float* __restrict__ x, const float* __restrict__ y,
    const float* __restrict__ g, const float* __restrict__ b,
    float* __restrict__ out,
    __nv_bfloat16* __restrict__ ohi, __nv_bfloat16* __restrict__ olo)
{
    const int row  = blockIdx.x * 8 + (threadIdx.x >> 5);
    const int lane = threadIdx.x & 31;
    const float* xr = x + (size_t)row * Dc;
    const float* yr = y + (size_t)row * Dc;

    float v[8];
    float s = 0.0f, s2 = 0.0f;
    #pragma unroll
    for (int i = 0; i < 8; i++) {
        float t = xr[i * 32 + lane] + yr[i * 32 + lane];
        v[i] = t;
        s += t;
        s2 = fmaf(t, t, s2);
    }
    #pragma unroll
    for (int o = 16; o > 0; o >>= 1) {
        s  += __shfl_xor_sync(0xFFFFFFFFu, s,  o);
        s2 += __shfl_xor_sync(0xFFFFFFFFu, s2, o);
    }
    float mu  = s * (1.0f / 256.0f);
    float var = s2 * (1.0f / 256.0f) - mu * mu;
    float r   = rsqrtf(var + 1e-5f);
    #pragma unroll
    for (int i = 0; i < 8; i++) {
        int c = i * 32 + lane;
        float o = (v[i] - mu) * r * g[c] + b[c];
        out[(size_t)row * Dc + c] = o;
        if (ohi) {
            __nv_bfloat16 h = __float2bfloat16(o);
            ohi[(size_t)row * Dc + c] = h;
            olo[(size_t)row * Dc + c] = __float2bfloat16(o - __bfloat162float(h));
        }
    }
}

// ---------------- launch ----------------
extern "C" void kernel_launch(void* const* d_in, const int* in_sizes, int n_in,
                              void* d_out, int out_size)
{
    const float* x    = (const float*)d_in[0];
    const int*   sb   = (const int*)d_in[1];
    const unsigned char* mask = (const unsigned char*)d_in[2];
    const float* Wq = (const float*)d_in[3];  const float* bq = (const float*)d_in[4];
    const float* Wk = (const float*)d_in[5];  const float* bk = (const float*)d_in[6];
    const float* Wv = (const float*)d_in[7];  const float* bv = (const float*)d_in[8];
    const float* Wo = (const float*)d_in[9];  const float* bo = (const float*)d_in[10];
    const float* be = (const float*)d_in[11];
    const float* g1 = (const float*)d_in[12]; const float* b1 = (const float*)d_in[13];
    const float* Wf1 = (const float*)d_in[14]; const float* bf1 = (const float*)d_in[15];
    const float* Wf2 = (const float*)d_in[16]; const float* bf2 = (const float*)d_in[17];
    const float* g2 = (const float*)d_in[18]; const float* b2 = (const float*)d_in[19];
    float* out = (float*)d_out;

    float *x1, *tmp;
    __nv_bfloat16 *xh, *xl, *qh, *ql, *kh, *kl, *vt, *aoh, *aol, *x1h, *x1l, *ffh, *ffl;
    __nv_bfloat16 *wqh, *wql, *wkh, *wkl, *wvh, *wvl, *woh, *wol, *wf1h, *wf1l, *wf2h, *wf2l;
    cudaGetSymbolAddress((void**)&x1,  g_x1);
    cudaGetSymbolAddress((void**)&tmp, g_tmp);
    cudaGetSymbolAddress((void**)&xh,  g_xh);  cudaGetSymbolAddress((void**)&xl,  g_xl);
    cudaGetSymbolAddress((void**)&qh,  g_qh);  cudaGetSymbolAddress((void**)&ql,  g_ql);
    cudaGetSymbolAddress((void**)&kh,  g_kh);  cudaGetSymbolAddress((void**)&kl,  g_kl);
    cudaGetSymbolAddress((void**)&vt,  g_vt);
    cudaGetSymbolAddress((void**)&aoh, g_aoh); cudaGetSymbolAddress((void**)&aol, g_aol);
    cudaGetSymbolAddress((void**)&x1h, g_x1h); cudaGetSymbolAddress((void**)&x1l, g_x1l);
    cudaGetSymbolAddress((void**)&ffh, g_ffh); cudaGetSymbolAddress((void**)&ffl, g_ffl);
    cudaGetSymbolAddress((void**)&wqh, g_wqh); cudaGetSymbolAddress((void**)&wql, g_wql);
    cudaGetSymbolAddress((void**)&wkh, g_wkh); cudaGetSymbolAddress((void**)&wkl, g_wkl);
    cudaGetSymbolAddress((void**)&wvh, g_wvh); cudaGetSymbolAddress((void**)&wvl, g_wvl);
    cudaGetSymbolAddress((void**)&woh, g_woh); cudaGetSymbolAddress((void**)&wol, g_wol);
    cudaGetSymbolAddress((void**)&wf1h, g_wf1h); cudaGetSymbolAddress((void**)&wf1l, g_wf1l);
    cudaGetSymbolAddress((void**)&wf2h, g_wf2h); cudaGetSymbolAddress((void**)&wf2l, g_wf2l);

    const int nX = Tc * Dc;
    dim3 gD (Dc / 64,     Tc / 128);   // (4, 64)
    dim3 gF1(4 * Dc / 64, Tc / 128);   // (16, 64)
    dim3 gVt(Tc / 64,     Dc / 128);   // (128, 2)

    split2_kernel<<<nX / 4 / 256, 256>>>(x, xh, xl, nX / 4);
    splitW_all<<<3072, 256>>>(Wq, Wk, Wv, Wo, Wf1, Wf2,
                              wqh, wql, wkh, wkl, wvh, wvl,
                              woh, wol, wf1h, wf1l, wf2h, wf2l);

    gemm_mma<<<gD, 256>>>(xh, xl, wqh, wql, bq, nullptr, qh, ql, Tc, Dc, Dc, 0, 1, 0);
    gemm_mma<<<gD, 256>>>(xh, xl, wkh, wkl, bk, nullptr, kh, kl, Tc, Dc, Dc, 0, 1, 0);
    gemm_mma<<<gVt, 256>>>(wvh, wvl, xh, xl, bv, nullptr, vt, nullptr, Dc, Tc, Dc, 0, 2, 1);

    attn_mma<<<dim3(Ec / 32, Bc, 2), 256>>>(qh, ql, kh, kl, vt, sb, mask, be, aoh, aol);

    gemm_mma<<<gD, 256>>>(aoh, aol, woh, wol, bo, tmp, nullptr, nullptr, Tc, Dc, Dc, 0, 0, 0);
    add_ln_kernel<<<Tc / 8, 256>>>(x, tmp, g1, b1, x1, x1h, x1l);

    gemm_mma<<<gF1, 256>>>(x1h, x1l, wf1h, wf1l, bf1, nullptr, ffh, ffl, Tc, 4 * Dc, Dc, 1, 1, 0);
    gemm_mma<<<gD, 256>>>(ffh, ffl, wf2h, wf2l, bf2, tmp, nullptr, nullptr, Tc, Dc, 4 * Dc, 0, 0, 0);
    add_ln_kernel<<<Tc / 8, 256>>>(x1, tmp, g2, b2, out, nullptr, nullptr);
}